// round 13
// baseline (speedup 1.0000x reference)
#include <cuda_runtime.h>
#include <cuda_bf16.h>
#include <cstdint>

#define BS 4
#define NSTK 32
#define NSPP 128
#define NPNT 4096
#define CIN 128
#define CU 256
#define COUT 256
#define KDN 10
#define NHALF 16
#define COOR 128
#define INF_F 3.402823466e+38f

#define OUT_OFF_DN 16384
#define OUT_OFF_COOR (16384 + 1048576)

// ---------------- static scratch ----------------
__device__ float g_spfd[BS * CIN * NSTK];
__device__ float g_xt[(size_t)BS * NPNT * CU];       // union_dense [b][n][c]
__device__ __nv_bfloat16 g_xh[(size_t)BS * NPNT * CU];
__device__ __nv_bfloat16 g_xl[(size_t)BS * NPNT * CU];
__device__ float g_sqd[BS * NPNT];
__device__ int   g_nbr[BS * NPNT * KDN];
__device__ __nv_bfloat16 g_wth[512 * 256];           // [Wd | W2]^T hi  [n][k]
__device__ __nv_bfloat16 g_wtl[512 * 256];           // lo
__device__ float g_A[(size_t)BS * NPNT * COUT];
__device__ float g_Bm[(size_t)BS * NPNT * COUT];
__device__ float g_dup[(size_t)BS * NPNT * COUT];
__device__ float g_xs[BS * NSTK * CU];
__device__ int   g_spnb[BS * NSTK * 2];
__device__ float g_sup[BS * COUT * NSTK];
__device__ int   g_fps[BS * NHALF];

#define MMA16816(C, A, B) \
    asm volatile("mma.sync.aligned.m16n8k16.row.col.f32.bf16.bf16.f32 " \
        "{%0,%1,%2,%3}, {%4,%5,%6,%7}, {%8,%9}, {%0,%1,%2,%3};" \
        : "+f"((C)[0]), "+f"((C)[1]), "+f"((C)[2]), "+f"((C)[3]) \
        : "r"((A)[0]), "r"((A)[1]), "r"((A)[2]), "r"((A)[3]), "r"((B)[0]), "r"((B)[1]))

#define LDMX4(R, ADDR) \
    asm volatile("ldmatrix.sync.aligned.m8n8.x4.shared.b16 {%0,%1,%2,%3}, [%4];" \
        : "=r"((R)[0]), "=r"((R)[1]), "=r"((R)[2]), "=r"((R)[3]) : "r"(ADDR))

#define LDMX2(R, ADDR) \
    asm volatile("ldmatrix.sync.aligned.m8n8.x2.shared.b16 {%0,%1}, [%2];" \
        : "=r"((R)[0]), "=r"((R)[1]) : "r"(ADDR))

#define PAD 40

// ---------------- W split + transpose: [Wd | W2]^T ----------------
__global__ void k_wsplit(const float* __restrict__ dnW) {
    int idx = blockIdx.x * 256 + threadIdx.x;        // 131072
    int k = idx & 255, n = idx >> 8;
    float v = (n < 256) ? dnW[k * 256 + n] - dnW[(k + 256) * 256 + n]
                        : dnW[(k + 256) * 256 + (n - 256)];
    __nv_bfloat16 h = __float2bfloat16(v);
    g_wth[idx] = h;
    g_wtl[idx] = __float2bfloat16(v - __bfloat162float(h));
}

// ---------------- FPS (exact reference loop) ----------------
__global__ void k_fps(const float* __restrict__ coor) {
    __shared__ float xs[NSTK][COOR];
    __shared__ float dist[NSTK];
    __shared__ int far_s;
    int b = blockIdx.x, tid = threadIdx.x;
    for (int e = tid; e < NSTK * COOR; e += 128)
        xs[e / COOR][e % COOR] = coor[(size_t)b * NSTK * COOR + e];
    if (tid < NSTK) dist[tid] = 1e10f;
    if (tid == 0) far_s = 0;
    __syncthreads();
    for (int it = 0; it < NHALF; ++it) {
        int far = far_s;
        if (tid == 0) g_fps[b * NHALF + it] = far;
        if (tid < NSTK) {
            float d = 0.f;
            for (int c = 0; c < COOR; ++c) { float t = xs[tid][c] - xs[far][c]; d += t * t; }
            dist[tid] = fminf(dist[tid], d);
        }
        __syncthreads();
        if (tid == 0) {
            float bd = dist[0]; int bi = 0;
            for (int j = 1; j < NSTK; ++j) if (dist[j] > bd) { bd = dist[j]; bi = j; }
            far_s = bi;
        }
        __syncthreads();
    }
}

// ---------------- DenseToSparse conv(1,3)+BN+relu+max ----------------
__global__ void __launch_bounds__(256) k_d2s(const float* __restrict__ dense,
                                             const float* __restrict__ w,
                                             const float* __restrict__ bias,
                                             const float* __restrict__ gg,
                                             const float* __restrict__ bt) {
    __shared__ float dfs[64][132];
    __shared__ float red[128];
    int b = blockIdx.x >> 5, s = blockIdx.x & 31;
    int tid = threadIdx.x;
    int o = tid & 127, half = tid >> 7;
    const float* src = dense + (size_t)b * CIN * NPNT + (size_t)s * NSPP;
    const float* wrow = w + (size_t)o * CIN * 3;
    float acc[64];
#pragma unroll
    for (int t = 0; t < 64; ++t) acc[t] = 0.f;
    for (int ch = 0; ch < 2; ++ch) {
        int ci = ch * 64;
        __syncthreads();
        for (int e = tid; e < 64 * 128; e += 256)
            dfs[e >> 7][e & 127] = src[(size_t)(ci + (e >> 7)) * NPNT + (e & 127)];
        if (tid < 64) {
            dfs[tid][128] = 0.f; dfs[tid][129] = 0.f;
            dfs[tid][130] = 0.f; dfs[tid][131] = 0.f;
        }
        __syncthreads();
        for (int i = 0; i < 64; ++i) {
            float w0 = __ldg(wrow + (ci + i) * 3 + 0);
            float w1 = __ldg(wrow + (ci + i) * 3 + 1);
            float w2 = __ldg(wrow + (ci + i) * 3 + 2);
#pragma unroll
            for (int pc = 0; pc < 8; ++pc) {
                const float4* dp = (const float4*)&dfs[i][half * 64 + pc * 8];
                float4 fa = dp[0], fb = dp[1], fc2 = dp[2];
                float d[10] = {fa.x, fa.y, fa.z, fa.w, fb.x, fb.y, fb.z, fb.w, fc2.x, fc2.y};
#pragma unroll
                for (int j = 0; j < 8; ++j)
                    acc[pc * 8 + j] += d[j] * w0 + d[j + 1] * w1 + d[j + 2] * w2;
            }
        }
    }
    float bo = bias[o], go = gg[o], bto = bt[o];
    float mx = -INF_F;
#pragma unroll
    for (int t = 0; t < 64; ++t) {
        int p = half * 64 + t;
        if (p < 126) {
            float h = go * (acc[t] + bo) + bto;
            mx = fmaxf(mx, h > 0.f ? h : 0.f);
        }
    }
    __syncthreads();
    if (half == 0) red[o] = mx;
    __syncthreads();
    if (half == 1)
        g_spfd[((size_t)b * CIN + o) * NSTK + s] = fmaxf(red[o], mx);
}

// ---------------- union_dense transpose ----------------
__global__ void k_txp(const float* __restrict__ dense) {
    __shared__ float tile[32][33];
    int b = blockIdx.z;
    int n0 = blockIdx.x * 32, c0 = blockIdx.y * 32;
    const float* src = dense + (size_t)b * CIN * NPNT;
    for (int j = threadIdx.y; j < 32; j += 8)
        tile[j][threadIdx.x] = src[(size_t)(c0 + j) * NPNT + n0 + threadIdx.x];
    __syncthreads();
    float* dst = g_xt + (size_t)b * NPNT * CU;
    for (int j = threadIdx.y; j < 32; j += 8)
        dst[(size_t)(n0 + j) * CU + c0 + threadIdx.x] = tile[threadIdx.x][j];
}

// ---------------- union_dense sparse broadcast ----------------
__global__ void k_fillsp(const float* __restrict__ sparse) {
    int idx = blockIdx.x * 256 + threadIdx.x;
    int c = idx & 127;
    int bn = idx >> 7;
    int n = bn & (NPNT - 1);
    int b = bn >> 12;
    g_xt[(size_t)(b * NPNT + n) * CU + CIN + c] =
        sparse[((size_t)b * CIN + c) * NSTK + (n >> 7)];
}

// ---------------- bf16 hi/lo split ----------------
__global__ void k_split() {
    size_t idx = (size_t)blockIdx.x * 256 + threadIdx.x;
    float x = g_xt[idx];
    __nv_bfloat16 h = __float2bfloat16(x);
    g_xh[idx] = h;
    g_xl[idx] = __float2bfloat16(x - __bfloat162float(h));
}

// ---------------- per-point squared norm ----------------
__global__ void k_sq() {
    int gw = (blockIdx.x * blockDim.x + threadIdx.x) >> 5;
    int lane = threadIdx.x & 31;
    if (gw >= BS * NPNT) return;
    const float* row = g_xt + (size_t)gw * CU;
    float s = 0.f;
    for (int c = lane; c < CU; c += 32) { float v = row[c]; s += v * v; }
#pragma unroll
    for (int off = 16; off; off >>= 1) s += __shfl_xor_sync(0xffffffffu, s, off);
    if (lane == 0) g_sqd[gw] = s;
}

// ---------------- fused gram + top-10: no dist matrix ----------------
// grid (32 row-tiles, BS), 256 threads, dynamic smem 107008 B
__global__ void __launch_bounds__(256) k_gram_topk() {
    extern __shared__ char dyn[];
    __nv_bfloat16* sAh = (__nv_bfloat16*)dyn;
    __nv_bfloat16* sAl = sAh + 128 * PAD;
    __nv_bfloat16* sBh = sAl + 128 * PAD;
    __nv_bfloat16* sBl = sBh + 128 * PAD;
    float* sD = (float*)(sBl + 128 * PAD);            // 128 x 129

    int b = blockIdx.y, ti = blockIdx.x;
    int i0 = ti * 128;
    const __nv_bfloat16* Xh = g_xh + (size_t)b * NPNT * CU;
    const __nv_bfloat16* Xl = g_xl + (size_t)b * NPNT * CU;
    int tid = threadIdx.x, w = tid >> 5, l = tid & 31;
    int wm = w >> 2, wn = w & 3;

    uint32_t uAh = (uint32_t)__cvta_generic_to_shared(sAh);
    uint32_t uAl = (uint32_t)__cvta_generic_to_shared(sAl);
    uint32_t uBh = (uint32_t)__cvta_generic_to_shared(sBh);
    uint32_t uBl = (uint32_t)__cvta_generic_to_shared(sBl);
    int arow = wm * 64 + ((l & 8) >> 3) * 8 + (l & 7);
    int acol = (l >> 4) * 8;
    int brow = wn * 32 + (l & 7);
    int bcol = ((l >> 3) & 1) * 8;
    int rl = l >> 2, cpair = (l & 3) * 2;

    const float* sqb = g_sqd + b * NPNT;
    float si[4][2];
#pragma unroll
    for (int mt = 0; mt < 4; ++mt) {
        si[mt][0] = sqb[i0 + wm * 64 + mt * 16 + rl];
        si[mt][1] = sqb[i0 + wm * 64 + mt * 16 + rl + 8];
    }

    float ld[10]; int li[10];
#pragma unroll
    for (int p = 0; p < 10; ++p) { ld[p] = INF_F; li[p] = 0x7fffffff; }

    for (int tj = 0; tj < 32; ++tj) {
        int j0 = tj * 128;
        float c[4][4][4];
#pragma unroll
        for (int mt = 0; mt < 4; ++mt)
#pragma unroll
            for (int nt = 0; nt < 4; ++nt)
#pragma unroll
                for (int q = 0; q < 4; ++q) c[mt][nt][q] = 0.f;

        for (int k0 = 0; k0 < CU; k0 += 32) {
            __syncthreads();
            for (int e = tid; e < 512; e += 256) {
                int row = e >> 2, seg = (e & 3) * 8;
                *(uint4*)&sAh[row * PAD + seg] = *(const uint4*)&Xh[(size_t)(i0 + row) * CU + k0 + seg];
                *(uint4*)&sAl[row * PAD + seg] = *(const uint4*)&Xl[(size_t)(i0 + row) * CU + k0 + seg];
                *(uint4*)&sBh[row * PAD + seg] = *(const uint4*)&Xh[(size_t)(j0 + row) * CU + k0 + seg];
                *(uint4*)&sBl[row * PAD + seg] = *(const uint4*)&Xl[(size_t)(j0 + row) * CU + k0 + seg];
            }
            __syncthreads();
#pragma unroll
            for (int ks = 0; ks < 2; ++ks) {
                uint32_t ah[4][4], al[4][4], bh[4][2], bl[4][2];
#pragma unroll
                for (int mt = 0; mt < 4; ++mt) {
                    uint32_t off = ((arow + mt * 16) * PAD + acol + ks * 16) * 2;
                    LDMX4(ah[mt], uAh + off);
                    LDMX4(al[mt], uAl + off);
                }
#pragma unroll
                for (int nt = 0; nt < 4; ++nt) {
                    uint32_t off = ((brow + nt * 8) * PAD + bcol + ks * 16) * 2;
                    LDMX2(bh[nt], uBh + off);
                    LDMX2(bl[nt], uBl + off);
                }
#pragma unroll
                for (int mt = 0; mt < 4; ++mt)
#pragma unroll
                    for (int nt = 0; nt < 4; ++nt) MMA16816(c[mt][nt], ah[mt], bh[nt]);
#pragma unroll
                for (int mt = 0; mt < 4; ++mt)
#pragma unroll
                    for (int nt = 0; nt < 4; ++nt) MMA16816(c[mt][nt], ah[mt], bl[nt]);
#pragma unroll
                for (int mt = 0; mt < 4; ++mt)
#pragma unroll
                    for (int nt = 0; nt < 4; ++nt) MMA16816(c[mt][nt], al[mt], bh[nt]);
            }
        }
        // stage dist tile in smem
#pragma unroll
        for (int nt = 0; nt < 4; ++nt) {
            int lc = wn * 32 + nt * 8 + cpair;
            float sj0 = sqb[j0 + lc], sj1 = sqb[j0 + lc + 1];
#pragma unroll
            for (int mt = 0; mt < 4; ++mt) {
                int lr0 = wm * 64 + mt * 16 + rl, lr1 = lr0 + 8;
                sD[lr0 * 129 + lc]     = si[mt][0] - 2.f * c[mt][nt][0] + sj0;
                sD[lr0 * 129 + lc + 1] = si[mt][0] - 2.f * c[mt][nt][1] + sj1;
                sD[lr1 * 129 + lc]     = si[mt][1] - 2.f * c[mt][nt][2] + sj0;
                sD[lr1 * 129 + lc + 1] = si[mt][1] - 2.f * c[mt][nt][3] + sj1;
            }
        }
        __syncthreads();
        if (tid < 128) {
            const float* row = sD + tid * 129;
            for (int j = 0; j < 128; ++j) {
                float dv = row[j];
                if (dv < ld[9]) {
                    ld[9] = dv; li[9] = j0 + j;
#pragma unroll
                    for (int p = 9; p >= 1; --p) {
                        bool sw = (ld[p] < ld[p - 1]) ||
                                  (ld[p] == ld[p - 1] && li[p] < li[p - 1]);
                        if (sw) {
                            float td = ld[p]; ld[p] = ld[p - 1]; ld[p - 1] = td;
                            int ti2 = li[p]; li[p] = li[p - 1]; li[p - 1] = ti2;
                        }
                    }
                }
            }
        }
    }
    if (tid < 128) {
        int* dst = g_nbr + ((size_t)b * NPNT + i0 + tid) * KDN;
#pragma unroll
        for (int t = 0; t < KDN; ++t) dst[t] = li[t];
    }
}

// ---------------- tensor-core GEMM: [A | Bm] = X @ [Wd | W2] ----------------
__global__ void __launch_bounds__(256) k_gemm_mma() {
    __shared__ __nv_bfloat16 sAh[128 * PAD], sAl[128 * PAD];
    __shared__ __nv_bfloat16 sBh[128 * PAD], sBl[128 * PAD];
    int jt = blockIdx.x, it = blockIdx.y;
    int i0 = it * 128, j0 = jt * 128;
    int tid = threadIdx.x, w = tid >> 5, l = tid & 31;
    int wm = w >> 2, wn = w & 3;
    float c[4][4][4];
#pragma unroll
    for (int mt = 0; mt < 4; ++mt)
#pragma unroll
        for (int nt = 0; nt < 4; ++nt)
#pragma unroll
            for (int q = 0; q < 4; ++q) c[mt][nt][q] = 0.f;

    uint32_t uAh = (uint32_t)__cvta_generic_to_shared(sAh);
    uint32_t uAl = (uint32_t)__cvta_generic_to_shared(sAl);
    uint32_t uBh = (uint32_t)__cvta_generic_to_shared(sBh);
    uint32_t uBl = (uint32_t)__cvta_generic_to_shared(sBl);
    int arow = wm * 64 + ((l & 8) >> 3) * 8 + (l & 7);
    int acol = (l >> 4) * 8;
    int brow = wn * 32 + (l & 7);
    int bcol = ((l >> 3) & 1) * 8;

    for (int k0 = 0; k0 < CU; k0 += 32) {
        __syncthreads();
        for (int e = tid; e < 512; e += 256) {
            int row = e >> 2, seg = (e & 3) * 8;
            *(uint4*)&sAh[row * PAD + seg] = *(const uint4*)&g_xh[(size_t)(i0 + row) * CU + k0 + seg];
            *(uint4*)&sAl[row * PAD + seg] = *(const uint4*)&g_xl[(size_t)(i0 + row) * CU + k0 + seg];
            *(uint4*)&sBh[row * PAD + seg] = *(const uint4*)&g_wth[(size_t)(j0 + row) * CU + k0 + seg];
            *(uint4*)&sBl[row * PAD + seg] = *(const uint4*)&g_wtl[(size_t)(j0 + row) * CU + k0 + seg];
        }
        __syncthreads();
#pragma unroll
        for (int ks = 0; ks < 2; ++ks) {
            uint32_t ah[4][4], al[4][4], bh[4][2], bl[4][2];
#pragma unroll
            for (int mt = 0; mt < 4; ++mt) {
                uint32_t off = ((arow + mt * 16) * PAD + acol + ks * 16) * 2;
                LDMX4(ah[mt], uAh + off);
                LDMX4(al[mt], uAl + off);
            }
#pragma unroll
            for (int nt = 0; nt < 4; ++nt) {
                uint32_t off = ((brow + nt * 8) * PAD + bcol + ks * 16) * 2;
                LDMX2(bh[nt], uBh + off);
                LDMX2(bl[nt], uBl + off);
            }
#pragma unroll
            for (int mt = 0; mt < 4; ++mt)
#pragma unroll
                for (int nt = 0; nt < 4; ++nt) MMA16816(c[mt][nt], ah[mt], bh[nt]);
#pragma unroll
            for (int mt = 0; mt < 4; ++mt)
#pragma unroll
                for (int nt = 0; nt < 4; ++nt) MMA16816(c[mt][nt], ah[mt], bl[nt]);
#pragma unroll
            for (int mt = 0; mt < 4; ++mt)
#pragma unroll
                for (int nt = 0; nt < 4; ++nt) MMA16816(c[mt][nt], al[mt], bh[nt]);
        }
    }
    int rl = l >> 2, cpair = (l & 3) * 2;
#pragma unroll
    for (int mt = 0; mt < 4; ++mt) {
        int gr0 = i0 + wm * 64 + mt * 16 + rl, gr1 = gr0 + 8;
#pragma unroll
        for (int nt = 0; nt < 4; ++nt) {
            int gc = j0 + wn * 32 + nt * 8 + cpair;
            float* Y = (gc < 256) ? g_A : g_Bm;
            int col = gc & 255;
            *(float2*)&Y[(size_t)gr0 * COUT + col] = make_float2(c[mt][nt][0], c[mt][nt][1]);
            *(float2*)&Y[(size_t)gr1 * COUT + col] = make_float2(c[mt][nt][2], c[mt][nt][3]);
        }
    }
}

// ---------------- dense combine ----------------
__global__ void k_dncomb(const float* __restrict__ bb, const float* __restrict__ gg,
                         const float* __restrict__ bt) {
    int bn = blockIdx.x;
    int o = threadIdx.x;
    int b = bn >> 12;
    float A = g_A[(size_t)bn * COUT + o] + bb[o];
    float go = gg[o], bto = bt[o];
    float mx = -INF_F;
    for (int k = 0; k < KDN; ++k) {
        int nb = g_nbr[bn * KDN + k];
        float h = go * (A + g_Bm[(size_t)(b * NPNT + nb) * COUT + o]) + bto;
        mx = fmaxf(mx, h > 0.f ? h : 0.f);
    }
    g_dup[(size_t)bn * COUT + o] = mx;
}

// ---------------- sparse GCN: xs + top-2 neighbors ----------------
__global__ void __launch_bounds__(256) k_spnbr(const float* __restrict__ sparse) {
    __shared__ float xs[NSTK][CU];
    __shared__ float sq[NSTK];
    int b = blockIdx.x, tid = threadIdx.x;
    for (int e = tid; e < NSTK * CU; e += 256) {
        int s = e >> 8, c = e & 255;
        float v = (c < CIN) ? sparse[((size_t)b * CIN + c) * NSTK + s]
                            : g_spfd[((size_t)b * CIN + (c - CIN)) * NSTK + s];
        xs[s][c] = v;
        g_xs[(size_t)(b * NSTK + s) * CU + c] = v;
    }
    __syncthreads();
    if (tid < NSTK) {
        float a = 0.f;
        for (int c = 0; c < CU; ++c) { float v = xs[tid][c]; a += v * v; }
        sq[tid] = a;
    }
    __syncthreads();
    if (tid < NSTK) {
        int r = tid;
        float d0 = INF_F, d1 = INF_F;
        int i0 = 0x7fffffff, i1 = 0x7fffffff;
        for (int m = 0; m < NSTK; ++m) {
            float dot = 0.f;
            for (int c = 0; c < CU; ++c) dot += xs[r][c] * xs[m][c];
            float d = sq[r] - 2.f * dot + sq[m];
            if (d < d0 || (d == d0 && m < i0)) { d1 = d0; i1 = i0; d0 = d; i0 = m; }
            else if (d < d1 || (d == d1 && m < i1)) { d1 = d; i1 = m; }
        }
        g_spnb[(b * NSTK + r) * 2 + 0] = i0;
        g_spnb[(b * NSTK + r) * 2 + 1] = i1;
    }
}

// ---------------- sparse edge-conv output ----------------
__global__ void __launch_bounds__(256) k_spout(const float* __restrict__ spW,
                                               const float* __restrict__ bb,
                                               const float* __restrict__ gg,
                                               const float* __restrict__ bt) {
    __shared__ float ctr[CU], n0v[CU], n1v[CU];
    int b = blockIdx.x >> 5, s = blockIdx.x & 31;
    int o = threadIdx.x;
    int m0 = g_spnb[(b * NSTK + s) * 2 + 0];
    int m1 = g_spnb[(b * NSTK + s) * 2 + 1];
    for (int c = o; c < CU; c += 256) {
        ctr[c] = g_xs[(size_t)(b * NSTK + s) * CU + c];
        n0v[c] = g_xs[(size_t)(b * NSTK + m0) * CU + c];
        n1v[c] = g_xs[(size_t)(b * NSTK + m1) * CU + c];
    }
    __syncthreads();
    float A = 0.f, B0 = 0.f, B1 = 0.f;
    for (int c = 0; c < CU; ++c) {
        float w1 = spW[(size_t)c * COUT + o];
        float w2 = spW[(size_t)(c + CU) * COUT + o];
        A += ctr[c] * (w1 - w2);
        B0 += n0v[c] * w2;
        B1 += n1v[c] * w2;
    }
    float bo = bb[o], go = gg[o], bto = bt[o];
    float h0 = go * (A + B0 + bo) + bto; h0 = h0 > 0.f ? h0 : 0.f;
    float h1 = go * (A + B1 + bo) + bto; h1 = h1 > 0.f ? h1 : 0.f;
    g_sup[((size_t)b * COUT + o) * NSTK + s] = fmaxf(h0, h1);
}

// ---------------- downsample conv ----------------
__global__ void __launch_bounds__(256) k_dsconv(const float* __restrict__ w,
                                                const float* __restrict__ bb,
                                                const float* __restrict__ gg,
                                                const float* __restrict__ bt,
                                                float* __restrict__ out) {
    __shared__ float dfs[64][36];
    int blk = blockIdx.x;
    int b = blk >> 6, jsel = (blk >> 2) & 15, pq = blk & 3;
    int o = threadIdx.x;
    int s = g_fps[b * NHALF + jsel];
    float acc[16];
#pragma unroll
    for (int p = 0; p < 16; ++p) acc[p] = 0.f;
    const float* wrow = w + (size_t)o * COUT * 3;
    for (int ch = 0; ch < 4; ++ch) {
        int c0 = ch * 64;
        __syncthreads();
        for (int e = o; e < 64 * 34; e += 256) {
            int ci = e & 63, qi = e >> 6;
            int q = pq * 32 - 1 + qi;
            dfs[ci][qi] = (q >= 0 && q < 128)
                ? g_dup[(size_t)(b * NPNT + s * NSPP + q) * COUT + c0 + ci] : 0.f;
        }
        __syncthreads();
        for (int ci = 0; ci < 64; ++ci) {
            float w0 = __ldg(wrow + (c0 + ci) * 3 + 0);
            float w1 = __ldg(wrow + (c0 + ci) * 3 + 1);
            float w2 = __ldg(wrow + (c0 + ci) * 3 + 2);
#pragma unroll
            for (int p = 0; p < 16; ++p)
                acc[p] += dfs[ci][2 * p] * w0 + dfs[ci][2 * p + 1] * w1 + dfs[ci][2 * p + 2] * w2;
        }
    }
    float bo = bb[o], go = gg[o], bto = bt[o];
    size_t base = OUT_OFF_DN + (((size_t)b * COUT + o) * NHALF + jsel) * 64 + pq * 16;
#pragma unroll
    for (int p = 0; p < 16; ++p) {
        float h = go * (acc[p] + bo) + bto;
        out[base + p] = h > 0.f ? h : 0.f;
    }
}

// ---------------- output gathers ----------------
__global__ void k_out_sp(float* __restrict__ out) {
    int idx = blockIdx.x * 256 + threadIdx.x;
    int j = idx & 15;
    int o = (idx >> 4) & 255;
    int b = idx >> 12;
    int s = g_fps[b * NHALF + j];
    out[idx] = g_sup[((size_t)b * COUT + o) * NSTK + s];
}

__global__ void k_out_coor(const float* __restrict__ coor, float* __restrict__ out) {
    int idx = blockIdx.x * 256 + threadIdx.x;
    int c = idx & 127;
    int j = (idx >> 7) & 15;
    int b = idx >> 11;
    int s = g_fps[b * NHALF + j];
    out[OUT_OFF_COOR + idx] = coor[((size_t)b * NSTK + s) * COOR + c];
}

extern "C" void kernel_launch(void* const* d_in, const int* in_sizes, int n_in,
                              void* d_out, int out_size) {
    const float* sparse = (const float*)d_in[0];
    const float* dense  = (const float*)d_in[1];
    const float* coor   = (const float*)d_in[2];
    const float* d2s_w  = (const float*)d_in[3];
    const float* d2s_b  = (const float*)d_in[4];
    const float* d2s_g  = (const float*)d_in[5];
    const float* d2s_bt = (const float*)d_in[6];
    const float* sp_W   = (const float*)d_in[7];
    const float* sp_b   = (const float*)d_in[8];
    const float* sp_g   = (const float*)d_in[9];
    const float* sp_bt  = (const float*)d_in[10];
    const float* dn_W   = (const float*)d_in[11];
    const float* dn_b   = (const float*)d_in[12];
    const float* dn_g   = (const float*)d_in[13];
    const float* dn_bt  = (const float*)d_in[14];
    const float* ds_w   = (const float*)d_in[15];
    const float* ds_b   = (const float*)d_in[16];
    const float* ds_g   = (const float*)d_in[17];
    const float* ds_bt  = (const float*)d_in[18];
    float* out = (float*)d_out;

    const int GRAM_SMEM = 4 * 128 * PAD * 2 + 128 * 129 * 4;   // 107008
    cudaFuncSetAttribute(k_gram_topk, cudaFuncAttributeMaxDynamicSharedMemorySize, GRAM_SMEM);

    k_wsplit<<<512, 256>>>(dn_W);
    k_fps<<<BS, 128>>>(coor);
    k_d2s<<<BS * NSTK, 256>>>(dense, d2s_w, d2s_b, d2s_g, d2s_bt);
    k_txp<<<dim3(NPNT / 32, CIN / 32, BS), dim3(32, 8)>>>(dense);
    k_fillsp<<<(BS * NPNT * CIN) / 256, 256>>>(sparse);
    k_split<<<(BS * NPNT * CU) / 256, 256>>>();
    k_sq<<<(BS * NPNT * 32) / 256, 256>>>();
    k_gram_topk<<<dim3(32, BS), 256, GRAM_SMEM>>>();
    k_gemm_mma<<<dim3(4, (BS * NPNT) / 128), 256>>>();
    k_dncomb<<<BS * NPNT, 256>>>(dn_b, dn_g, dn_bt);
    k_spnbr<<<BS, 256>>>(sparse);
    k_spout<<<BS * NSTK, 256>>>(sp_W, sp_b, sp_g, sp_bt);
    k_dsconv<<<BS * NHALF * 4, 256>>>(ds_w, ds_b, ds_g, ds_bt, out);
    k_out_sp<<<64, 256>>>(out);
    k_out_coor<<<32, 256>>>(coor, out);
}

// round 15
// speedup vs baseline: 1.3936x; 1.3936x over previous
#include <cuda_runtime.h>
#include <cuda_bf16.h>
#include <cstdint>

#define BS 4
#define NSTK 32
#define NSPP 128
#define NPNT 4096
#define CIN 128
#define CU 256
#define COUT 256
#define KDN 10
#define NHALF 16
#define COOR 128
#define INF_F 3.402823466e+38f

#define OUT_OFF_DN 16384
#define OUT_OFF_COOR (16384 + 1048576)

// ---------------- static scratch ----------------
__device__ float g_spfd[BS * CIN * NSTK];
__device__ float g_xt[(size_t)BS * NPNT * CU];       // union_dense [b][n][c]
__device__ __nv_bfloat16 g_xh[(size_t)BS * NPNT * CU];
__device__ __nv_bfloat16 g_xl[(size_t)BS * NPNT * CU];
__device__ float g_sqd[BS * NPNT];
__device__ float g_dist[(size_t)BS * NPNT * NPNT];   // 256 MB
__device__ int   g_nbr[BS * NPNT * KDN];
__device__ __nv_bfloat16 g_wth[512 * 256];           // [Wd | W2]^T hi  [n][k]
__device__ __nv_bfloat16 g_wtl[512 * 256];           // lo
__device__ float g_A[(size_t)BS * NPNT * COUT];
__device__ float g_Bm[(size_t)BS * NPNT * COUT];
__device__ float g_dup[(size_t)BS * NPNT * COUT];
__device__ float g_xs[BS * NSTK * CU];
__device__ int   g_spnb[BS * NSTK * 2];
__device__ float g_sup[BS * COUT * NSTK];
__device__ int   g_fps[BS * NHALF];

#define MMA16816(C, A, B) \
    asm volatile("mma.sync.aligned.m16n8k16.row.col.f32.bf16.bf16.f32 " \
        "{%0,%1,%2,%3}, {%4,%5,%6,%7}, {%8,%9}, {%0,%1,%2,%3};" \
        : "+f"((C)[0]), "+f"((C)[1]), "+f"((C)[2]), "+f"((C)[3]) \
        : "r"((A)[0]), "r"((A)[1]), "r"((A)[2]), "r"((A)[3]), "r"((B)[0]), "r"((B)[1]))

#define LDMX4(R, ADDR) \
    asm volatile("ldmatrix.sync.aligned.m8n8.x4.shared.b16 {%0,%1,%2,%3}, [%4];" \
        : "=r"((R)[0]), "=r"((R)[1]), "=r"((R)[2]), "=r"((R)[3]) : "r"(ADDR))

#define LDMX2(R, ADDR) \
    asm volatile("ldmatrix.sync.aligned.m8n8.x2.shared.b16 {%0,%1}, [%2];" \
        : "=r"((R)[0]), "=r"((R)[1]) : "r"(ADDR))

#define PAD 40

// ---------------- W split + transpose: [Wd | W2]^T ----------------
__global__ void k_wsplit(const float* __restrict__ dnW) {
    int idx = blockIdx.x * 256 + threadIdx.x;        // 131072
    int k = idx & 255, n = idx >> 8;
    float v = (n < 256) ? dnW[k * 256 + n] - dnW[(k + 256) * 256 + n]
                        : dnW[(k + 256) * 256 + (n - 256)];
    __nv_bfloat16 h = __float2bfloat16(v);
    g_wth[idx] = h;
    g_wtl[idx] = __float2bfloat16(v - __bfloat162float(h));
}

// ---------------- FPS (exact reference loop) ----------------
__global__ void k_fps(const float* __restrict__ coor) {
    __shared__ float xs[NSTK][COOR];
    __shared__ float dist[NSTK];
    __shared__ int far_s;
    int b = blockIdx.x, tid = threadIdx.x;
    for (int e = tid; e < NSTK * COOR; e += 128)
        xs[e / COOR][e % COOR] = coor[(size_t)b * NSTK * COOR + e];
    if (tid < NSTK) dist[tid] = 1e10f;
    if (tid == 0) far_s = 0;
    __syncthreads();
    for (int it = 0; it < NHALF; ++it) {
        int far = far_s;
        if (tid == 0) g_fps[b * NHALF + it] = far;
        if (tid < NSTK) {
            float d = 0.f;
            for (int c = 0; c < COOR; ++c) { float t = xs[tid][c] - xs[far][c]; d += t * t; }
            dist[tid] = fminf(dist[tid], d);
        }
        __syncthreads();
        if (tid == 0) {
            float bd = dist[0]; int bi = 0;
            for (int j = 1; j < NSTK; ++j) if (dist[j] > bd) { bd = dist[j]; bi = j; }
            far_s = bi;
        }
        __syncthreads();
    }
}

// ---------------- DenseToSparse conv(1,3)+BN+relu+max ----------------
__global__ void __launch_bounds__(256) k_d2s(const float* __restrict__ dense,
                                             const float* __restrict__ w,
                                             const float* __restrict__ bias,
                                             const float* __restrict__ gg,
                                             const float* __restrict__ bt) {
    __shared__ float dfs[64][132];
    __shared__ float red[128];
    int b = blockIdx.x >> 5, s = blockIdx.x & 31;
    int tid = threadIdx.x;
    int o = tid & 127, half = tid >> 7;
    const float* src = dense + (size_t)b * CIN * NPNT + (size_t)s * NSPP;
    const float* wrow = w + (size_t)o * CIN * 3;
    float acc[64];
#pragma unroll
    for (int t = 0; t < 64; ++t) acc[t] = 0.f;
    for (int ch = 0; ch < 2; ++ch) {
        int ci = ch * 64;
        __syncthreads();
        for (int e = tid; e < 64 * 128; e += 256)
            dfs[e >> 7][e & 127] = src[(size_t)(ci + (e >> 7)) * NPNT + (e & 127)];
        if (tid < 64) {
            dfs[tid][128] = 0.f; dfs[tid][129] = 0.f;
            dfs[tid][130] = 0.f; dfs[tid][131] = 0.f;
        }
        __syncthreads();
        for (int i = 0; i < 64; ++i) {
            float w0 = __ldg(wrow + (ci + i) * 3 + 0);
            float w1 = __ldg(wrow + (ci + i) * 3 + 1);
            float w2 = __ldg(wrow + (ci + i) * 3 + 2);
#pragma unroll
            for (int pc = 0; pc < 8; ++pc) {
                const float4* dp = (const float4*)&dfs[i][half * 64 + pc * 8];
                float4 fa = dp[0], fb = dp[1], fc2 = dp[2];
                float d[10] = {fa.x, fa.y, fa.z, fa.w, fb.x, fb.y, fb.z, fb.w, fc2.x, fc2.y};
#pragma unroll
                for (int j = 0; j < 8; ++j)
                    acc[pc * 8 + j] += d[j] * w0 + d[j + 1] * w1 + d[j + 2] * w2;
            }
        }
    }
    float bo = bias[o], go = gg[o], bto = bt[o];
    float mx = -INF_F;
#pragma unroll
    for (int t = 0; t < 64; ++t) {
        int p = half * 64 + t;
        if (p < 126) {
            float h = go * (acc[t] + bo) + bto;
            mx = fmaxf(mx, h > 0.f ? h : 0.f);
        }
    }
    __syncthreads();
    if (half == 0) red[o] = mx;
    __syncthreads();
    if (half == 1)
        g_spfd[((size_t)b * CIN + o) * NSTK + s] = fmaxf(red[o], mx);
}

// ---------------- union_dense transpose ----------------
__global__ void k_txp(const float* __restrict__ dense) {
    __shared__ float tile[32][33];
    int b = blockIdx.z;
    int n0 = blockIdx.x * 32, c0 = blockIdx.y * 32;
    const float* src = dense + (size_t)b * CIN * NPNT;
    for (int j = threadIdx.y; j < 32; j += 8)
        tile[j][threadIdx.x] = src[(size_t)(c0 + j) * NPNT + n0 + threadIdx.x];
    __syncthreads();
    float* dst = g_xt + (size_t)b * NPNT * CU;
    for (int j = threadIdx.y; j < 32; j += 8)
        dst[(size_t)(n0 + j) * CU + c0 + threadIdx.x] = tile[threadIdx.x][j];
}

// ---------------- union_dense sparse broadcast ----------------
__global__ void k_fillsp(const float* __restrict__ sparse) {
    int idx = blockIdx.x * 256 + threadIdx.x;
    int c = idx & 127;
    int bn = idx >> 7;
    int n = bn & (NPNT - 1);
    int b = bn >> 12;
    g_xt[(size_t)(b * NPNT + n) * CU + CIN + c] =
        sparse[((size_t)b * CIN + c) * NSTK + (n >> 7)];
}

// ---------------- bf16 hi/lo split ----------------
__global__ void k_split() {
    size_t idx = (size_t)blockIdx.x * 256 + threadIdx.x;
    float x = g_xt[idx];
    __nv_bfloat16 h = __float2bfloat16(x);
    g_xh[idx] = h;
    g_xl[idx] = __float2bfloat16(x - __bfloat162float(h));
}

// ---------------- per-point squared norm ----------------
__global__ void k_sq() {
    int gw = (blockIdx.x * blockDim.x + threadIdx.x) >> 5;
    int lane = threadIdx.x & 31;
    if (gw >= BS * NPNT) return;
    const float* row = g_xt + (size_t)gw * CU;
    float s = 0.f;
    for (int c = lane; c < CU; c += 32) { float v = row[c]; s += v * v; }
#pragma unroll
    for (int off = 16; off; off >>= 1) s += __shfl_xor_sync(0xffffffffu, s, off);
    if (lane == 0) g_sqd[gw] = s;
}

// ---------------- tensor-core gram: bf16-split, symmetric, fused mirror ----------------
__global__ void __launch_bounds__(256) k_gram_mma() {
    __shared__ __nv_bfloat16 sAh[128 * PAD], sAl[128 * PAD];
    __shared__ __nv_bfloat16 sBh[128 * PAD], sBl[128 * PAD];
    int b = blockIdx.z, ti = blockIdx.y, tj = blockIdx.x;
    if (ti > tj) return;
    bool mirror = (ti != tj);
    int i0 = ti * 128, j0 = tj * 128;
    const __nv_bfloat16* Xh = g_xh + (size_t)b * NPNT * CU;
    const __nv_bfloat16* Xl = g_xl + (size_t)b * NPNT * CU;
    int tid = threadIdx.x, w = tid >> 5, l = tid & 31;
    int wm = w >> 2, wn = w & 3;
    float c[4][4][4];
#pragma unroll
    for (int mt = 0; mt < 4; ++mt)
#pragma unroll
        for (int nt = 0; nt < 4; ++nt)
#pragma unroll
            for (int q = 0; q < 4; ++q) c[mt][nt][q] = 0.f;

    uint32_t uAh = (uint32_t)__cvta_generic_to_shared(sAh);
    uint32_t uAl = (uint32_t)__cvta_generic_to_shared(sAl);
    uint32_t uBh = (uint32_t)__cvta_generic_to_shared(sBh);
    uint32_t uBl = (uint32_t)__cvta_generic_to_shared(sBl);
    int arow = wm * 64 + ((l & 8) >> 3) * 8 + (l & 7);
    int acol = (l >> 4) * 8;
    int brow = wn * 32 + (l & 7);
    int bcol = ((l >> 3) & 1) * 8;

    for (int k0 = 0; k0 < CU; k0 += 32) {
        __syncthreads();
        for (int e = tid; e < 512; e += 256) {
            int row = e >> 2, seg = (e & 3) * 8;
            *(uint4*)&sAh[row * PAD + seg] = *(const uint4*)&Xh[(size_t)(i0 + row) * CU + k0 + seg];
            *(uint4*)&sAl[row * PAD + seg] = *(const uint4*)&Xl[(size_t)(i0 + row) * CU + k0 + seg];
            *(uint4*)&sBh[row * PAD + seg] = *(const uint4*)&Xh[(size_t)(j0 + row) * CU + k0 + seg];
            *(uint4*)&sBl[row * PAD + seg] = *(const uint4*)&Xl[(size_t)(j0 + row) * CU + k0 + seg];
        }
        __syncthreads();
#pragma unroll
        for (int ks = 0; ks < 2; ++ks) {
            uint32_t ah[4][4], al[4][4], bh[4][2], bl[4][2];
#pragma unroll
            for (int mt = 0; mt < 4; ++mt) {
                uint32_t off = ((arow + mt * 16) * PAD + acol + ks * 16) * 2;
                LDMX4(ah[mt], uAh + off);
                LDMX4(al[mt], uAl + off);
            }
#pragma unroll
            for (int nt = 0; nt < 4; ++nt) {
                uint32_t off = ((brow + nt * 8) * PAD + bcol + ks * 16) * 2;
                LDMX2(bh[nt], uBh + off);
                LDMX2(bl[nt], uBl + off);
            }
#pragma unroll
            for (int mt = 0; mt < 4; ++mt)
#pragma unroll
                for (int nt = 0; nt < 4; ++nt) MMA16816(c[mt][nt], ah[mt], bh[nt]);
#pragma unroll
            for (int mt = 0; mt < 4; ++mt)
#pragma unroll
                for (int nt = 0; nt < 4; ++nt) MMA16816(c[mt][nt], ah[mt], bl[nt]);
#pragma unroll
            for (int mt = 0; mt < 4; ++mt)
#pragma unroll
                for (int nt = 0; nt < 4; ++nt) MMA16816(c[mt][nt], al[mt], bh[nt]);
        }
    }
    const float* sqb = g_sqd + b * NPNT;
    float* D = g_dist + (size_t)b * NPNT * NPNT;
    int rl = l >> 2, cpair = (l & 3) * 2;
#pragma unroll
    for (int mt = 0; mt < 4; ++mt) {
        int gr0 = i0 + wm * 64 + mt * 16 + rl, gr1 = gr0 + 8;
        float si0 = sqb[gr0], si1 = sqb[gr1];
#pragma unroll
        for (int nt = 0; nt < 4; ++nt) {
            int gc = j0 + wn * 32 + nt * 8 + cpair;
            float sj0 = sqb[gc], sj1 = sqb[gc + 1];
            float d00 = si0 - 2.f * c[mt][nt][0] + sj0;
            float d01 = si0 - 2.f * c[mt][nt][1] + sj1;
            float d10 = si1 - 2.f * c[mt][nt][2] + sj0;
            float d11 = si1 - 2.f * c[mt][nt][3] + sj1;
            *(float2*)&D[(size_t)gr0 * NPNT + gc] = make_float2(d00, d01);
            *(float2*)&D[(size_t)gr1 * NPNT + gc] = make_float2(d10, d11);
            if (mirror) {
                // transposed writes: 8 lanes (same l&3) cover 8 consecutive cols = 1 sector
                D[(size_t)gc * NPNT + gr0]       = d00;
                D[(size_t)gc * NPNT + gr1]       = d10;
                D[(size_t)(gc + 1) * NPNT + gr0] = d01;
                D[(size_t)(gc + 1) * NPNT + gr1] = d11;
            }
        }
    }
}

// ---------------- top-10 smallest per row (warp/row, stable ties) ----------------
__global__ void k_topk() {
    int gw = (blockIdx.x * blockDim.x + threadIdx.x) >> 5;
    int lane = threadIdx.x & 31;
    if (gw >= BS * NPNT) return;
    const float* drow = g_dist + (size_t)gw * NPNT;
    float ld[10]; int li[10];
#pragma unroll
    for (int p = 0; p < 10; ++p) { ld[p] = INF_F; li[p] = 0x7fffffff; }
    for (int j = lane; j < NPNT; j += 32) {
        float dv = drow[j];
        if (dv < ld[9] || (dv == ld[9] && j < li[9])) {
            ld[9] = dv; li[9] = j;
#pragma unroll
            for (int p = 9; p >= 1; --p) {
                bool sw = (ld[p] < ld[p - 1]) || (ld[p] == ld[p - 1] && li[p] < li[p - 1]);
                if (sw) {
                    float td = ld[p]; ld[p] = ld[p - 1]; ld[p - 1] = td;
                    int ti = li[p]; li[p] = li[p - 1]; li[p - 1] = ti;
                }
            }
        }
    }
    int ptr = 0;
    for (int t = 0; t < KDN; ++t) {
        float cd = INF_F; int ci = 0x7fffffff;
#pragma unroll
        for (int p = 0; p < 10; ++p) if (p == ptr) { cd = ld[p]; ci = li[p]; }
        float wd = cd; int wi = ci;
#pragma unroll
        for (int off = 16; off; off >>= 1) {
            float od = __shfl_xor_sync(0xffffffffu, wd, off);
            int oi = __shfl_xor_sync(0xffffffffu, wi, off);
            if (od < wd || (od == wd && oi < wi)) { wd = od; wi = oi; }
        }
        if (ci == wi) ptr++;
        if (lane == 0) g_nbr[gw * KDN + t] = wi;
    }
}

// ---------------- tensor-core GEMM: [A | Bm] = X @ [Wd | W2] ----------------
__global__ void __launch_bounds__(256) k_gemm_mma() {
    __shared__ __nv_bfloat16 sAh[128 * PAD], sAl[128 * PAD];
    __shared__ __nv_bfloat16 sBh[128 * PAD], sBl[128 * PAD];
    int jt = blockIdx.x, it = blockIdx.y;
    int i0 = it * 128, j0 = jt * 128;
    int tid = threadIdx.x, w = tid >> 5, l = tid & 31;
    int wm = w >> 2, wn = w & 3;
    float c[4][4][4];
#pragma unroll
    for (int mt = 0; mt < 4; ++mt)
#pragma unroll
        for (int nt = 0; nt < 4; ++nt)
#pragma unroll
            for (int q = 0; q < 4; ++q) c[mt][nt][q] = 0.f;

    uint32_t uAh = (uint32_t)__cvta_generic_to_shared(sAh);
    uint32_t uAl = (uint32_t)__cvta_generic_to_shared(sAl);
    uint32_t uBh = (uint32_t)__cvta_generic_to_shared(sBh);
    uint32_t uBl = (uint32_t)__cvta_generic_to_shared(sBl);
    int arow = wm * 64 + ((l & 8) >> 3) * 8 + (l & 7);
    int acol = (l >> 4) * 8;
    int brow = wn * 32 + (l & 7);
    int bcol = ((l >> 3) & 1) * 8;

    for (int k0 = 0; k0 < CU; k0 += 32) {
        __syncthreads();
        for (int e = tid; e < 512; e += 256) {
            int row = e >> 2, seg = (e & 3) * 8;
            *(uint4*)&sAh[row * PAD + seg] = *(const uint4*)&g_xh[(size_t)(i0 + row) * CU + k0 + seg];
            *(uint4*)&sAl[row * PAD + seg] = *(const uint4*)&g_xl[(size_t)(i0 + row) * CU + k0 + seg];
            *(uint4*)&sBh[row * PAD + seg] = *(const uint4*)&g_wth[(size_t)(j0 + row) * CU + k0 + seg];
            *(uint4*)&sBl[row * PAD + seg] = *(const uint4*)&g_wtl[(size_t)(j0 + row) * CU + k0 + seg];
        }
        __syncthreads();
#pragma unroll
        for (int ks = 0; ks < 2; ++ks) {
            uint32_t ah[4][4], al[4][4], bh[4][2], bl[4][2];
#pragma unroll
            for (int mt = 0; mt < 4; ++mt) {
                uint32_t off = ((arow + mt * 16) * PAD + acol + ks * 16) * 2;
                LDMX4(ah[mt], uAh + off);
                LDMX4(al[mt], uAl + off);
            }
#pragma unroll
            for (int nt = 0; nt < 4; ++nt) {
                uint32_t off = ((brow + nt * 8) * PAD + bcol + ks * 16) * 2;
                LDMX2(bh[nt], uBh + off);
                LDMX2(bl[nt], uBl + off);
            }
#pragma unroll
            for (int mt = 0; mt < 4; ++mt)
#pragma unroll
                for (int nt = 0; nt < 4; ++nt) MMA16816(c[mt][nt], ah[mt], bh[nt]);
#pragma unroll
            for (int mt = 0; mt < 4; ++mt)
#pragma unroll
                for (int nt = 0; nt < 4; ++nt) MMA16816(c[mt][nt], ah[mt], bl[nt]);
#pragma unroll
            for (int mt = 0; mt < 4; ++mt)
#pragma unroll
                for (int nt = 0; nt < 4; ++nt) MMA16816(c[mt][nt], al[mt], bh[nt]);
        }
    }
    int rl = l >> 2, cpair = (l & 3) * 2;
#pragma unroll
    for (int mt = 0; mt < 4; ++mt) {
        int gr0 = i0 + wm * 64 + mt * 16 + rl, gr1 = gr0 + 8;
#pragma unroll
        for (int nt = 0; nt < 4; ++nt) {
            int gc = j0 + wn * 32 + nt * 8 + cpair;
            float* Y = (gc < 256) ? g_A : g_Bm;
            int col = gc & 255;
            *(float2*)&Y[(size_t)gr0 * COUT + col] = make_float2(c[mt][nt][0], c[mt][nt][1]);
            *(float2*)&Y[(size_t)gr1 * COUT + col] = make_float2(c[mt][nt][2], c[mt][nt][3]);
        }
    }
}

// ---------------- dense combine ----------------
__global__ void k_dncomb(const float* __restrict__ bb, const float* __restrict__ gg,
                         const float* __restrict__ bt) {
    int bn = blockIdx.x;
    int o = threadIdx.x;
    int b = bn >> 12;
    float A = g_A[(size_t)bn * COUT + o] + bb[o];
    float go = gg[o], bto = bt[o];
    float mx = -INF_F;
    for (int k = 0; k < KDN; ++k) {
        int nb = g_nbr[bn * KDN + k];
        float h = go * (A + g_Bm[(size_t)(b * NPNT + nb) * COUT + o]) + bto;
        mx = fmaxf(mx, h > 0.f ? h : 0.f);
    }
    g_dup[(size_t)bn * COUT + o] = mx;
}

// ---------------- sparse GCN: xs + top-2 neighbors ----------------
__global__ void __launch_bounds__(256) k_spnbr(const float* __restrict__ sparse) {
    __shared__ float xs[NSTK][CU];
    __shared__ float sq[NSTK];
    int b = blockIdx.x, tid = threadIdx.x;
    for (int e = tid; e < NSTK * CU; e += 256) {
        int s = e >> 8, c = e & 255;
        float v = (c < CIN) ? sparse[((size_t)b * CIN + c) * NSTK + s]
                            : g_spfd[((size_t)b * CIN + (c - CIN)) * NSTK + s];
        xs[s][c] = v;
        g_xs[(size_t)(b * NSTK + s) * CU + c] = v;
    }
    __syncthreads();
    if (tid < NSTK) {
        float a = 0.f;
        for (int c = 0; c < CU; ++c) { float v = xs[tid][c]; a += v * v; }
        sq[tid] = a;
    }
    __syncthreads();
    if (tid < NSTK) {
        int r = tid;
        float d0 = INF_F, d1 = INF_F;
        int i0 = 0x7fffffff, i1 = 0x7fffffff;
        for (int m = 0; m < NSTK; ++m) {
            float dot = 0.f;
            for (int c = 0; c < CU; ++c) dot += xs[r][c] * xs[m][c];
            float d = sq[r] - 2.f * dot + sq[m];
            if (d < d0 || (d == d0 && m < i0)) { d1 = d0; i1 = i0; d0 = d; i0 = m; }
            else if (d < d1 || (d == d1 && m < i1)) { d1 = d; i1 = m; }
        }
        g_spnb[(b * NSTK + r) * 2 + 0] = i0;
        g_spnb[(b * NSTK + r) * 2 + 1] = i1;
    }
}

// ---------------- sparse edge-conv output ----------------
__global__ void __launch_bounds__(256) k_spout(const float* __restrict__ spW,
                                               const float* __restrict__ bb,
                                               const float* __restrict__ gg,
                                               const float* __restrict__ bt) {
    __shared__ float ctr[CU], n0v[CU], n1v[CU];
    int b = blockIdx.x >> 5, s = blockIdx.x & 31;
    int o = threadIdx.x;
    int m0 = g_spnb[(b * NSTK + s) * 2 + 0];
    int m1 = g_spnb[(b * NSTK + s) * 2 + 1];
    for (int c = o; c < CU; c += 256) {
        ctr[c] = g_xs[(size_t)(b * NSTK + s) * CU + c];
        n0v[c] = g_xs[(size_t)(b * NSTK + m0) * CU + c];
        n1v[c] = g_xs[(size_t)(b * NSTK + m1) * CU + c];
    }
    __syncthreads();
    float A = 0.f, B0 = 0.f, B1 = 0.f;
    for (int c = 0; c < CU; ++c) {
        float w1 = spW[(size_t)c * COUT + o];
        float w2 = spW[(size_t)(c + CU) * COUT + o];
        A += ctr[c] * (w1 - w2);
        B0 += n0v[c] * w2;
        B1 += n1v[c] * w2;
    }
    float bo = bb[o], go = gg[o], bto = bt[o];
    float h0 = go * (A + B0 + bo) + bto; h0 = h0 > 0.f ? h0 : 0.f;
    float h1 = go * (A + B1 + bo) + bto; h1 = h1 > 0.f ? h1 : 0.f;
    g_sup[((size_t)b * COUT + o) * NSTK + s] = fmaxf(h0, h1);
}

// ---------------- downsample conv ----------------
__global__ void __launch_bounds__(256) k_dsconv(const float* __restrict__ w,
                                                const float* __restrict__ bb,
                                                const float* __restrict__ gg,
                                                const float* __restrict__ bt,
                                                float* __restrict__ out) {
    __shared__ float dfs[64][36];
    int blk = blockIdx.x;
    int b = blk >> 6, jsel = (blk >> 2) & 15, pq = blk & 3;
    int o = threadIdx.x;
    int s = g_fps[b * NHALF + jsel];
    float acc[16];
#pragma unroll
    for (int p = 0; p < 16; ++p) acc[p] = 0.f;
    const float* wrow = w + (size_t)o * COUT * 3;
    for (int ch = 0; ch < 4; ++ch) {
        int c0 = ch * 64;
        __syncthreads();
        for (int e = o; e < 64 * 34; e += 256) {
            int ci = e & 63, qi = e >> 6;
            int q = pq * 32 - 1 + qi;
            dfs[ci][qi] = (q >= 0 && q < 128)
                ? g_dup[(size_t)(b * NPNT + s * NSPP + q) * COUT + c0 + ci] : 0.f;
        }
        __syncthreads();
        for (int ci = 0; ci < 64; ++ci) {
            float w0 = __ldg(wrow + (c0 + ci) * 3 + 0);
            float w1 = __ldg(wrow + (c0 + ci) * 3 + 1);
            float w2 = __ldg(wrow + (c0 + ci) * 3 + 2);
#pragma unroll
            for (int p = 0; p < 16; ++p)
                acc[p] += dfs[ci][2 * p] * w0 + dfs[ci][2 * p + 1] * w1 + dfs[ci][2 * p + 2] * w2;
        }
    }
    float bo = bb[o], go = gg[o], bto = bt[o];
    size_t base = OUT_OFF_DN + (((size_t)b * COUT + o) * NHALF + jsel) * 64 + pq * 16;
#pragma unroll
    for (int p = 0; p < 16; ++p) {
        float h = go * (acc[p] + bo) + bto;
        out[base + p] = h > 0.f ? h : 0.f;
    }
}

// ---------------- output gathers ----------------
__global__ void k_out_sp(float* __restrict__ out) {
    int idx = blockIdx.x * 256 + threadIdx.x;
    int j = idx & 15;
    int o = (idx >> 4) & 255;
    int b = idx >> 12;
    int s = g_fps[b * NHALF + j];
    out[idx] = g_sup[((size_t)b * COUT + o) * NSTK + s];
}

__global__ void k_out_coor(const float* __restrict__ coor, float* __restrict__ out) {
    int idx = blockIdx.x * 256 + threadIdx.x;
    int c = idx & 127;
    int j = (idx >> 7) & 15;
    int b = idx >> 11;
    int s = g_fps[b * NHALF + j];
    out[OUT_OFF_COOR + idx] = coor[((size_t)b * NSTK + s) * COOR + c];
}

extern "C" void kernel_launch(void* const* d_in, const int* in_sizes, int n_in,
                              void* d_out, int out_size) {
    const float* sparse = (const float*)d_in[0];
    const float* dense  = (const float*)d_in[1];
    const float* coor   = (const float*)d_in[2];
    const float* d2s_w  = (const float*)d_in[3];
    const float* d2s_b  = (const float*)d_in[4];
    const float* d2s_g  = (const float*)d_in[5];
    const float* d2s_bt = (const float*)d_in[6];
    const float* sp_W   = (const float*)d_in[7];
    const float* sp_b   = (const float*)d_in[8];
    const float* sp_g   = (const float*)d_in[9];
    const float* sp_bt  = (const float*)d_in[10];
    const float* dn_W   = (const float*)d_in[11];
    const float* dn_b   = (const float*)d_in[12];
    const float* dn_g   = (const float*)d_in[13];
    const float* dn_bt  = (const float*)d_in[14];
    const float* ds_w   = (const float*)d_in[15];
    const float* ds_b   = (const float*)d_in[16];
    const float* ds_g   = (const float*)d_in[17];
    const float* ds_bt  = (const float*)d_in[18];
    float* out = (float*)d_out;

    k_wsplit<<<512, 256>>>(dn_W);
    k_fps<<<BS, 128>>>(coor);
    k_d2s<<<BS * NSTK, 256>>>(dense, d2s_w, d2s_b, d2s_g, d2s_bt);
    k_txp<<<dim3(NPNT / 32, CIN / 32, BS), dim3(32, 8)>>>(dense);
    k_fillsp<<<(BS * NPNT * CIN) / 256, 256>>>(sparse);
    k_split<<<(BS * NPNT * CU) / 256, 256>>>();
    k_sq<<<(BS * NPNT * 32) / 256, 256>>>();
    k_gram_mma<<<dim3(32, 32, BS), 256>>>();
    k_topk<<<(BS * NPNT * 32) / 256, 256>>>();
    k_gemm_mma<<<dim3(4, (BS * NPNT) / 128), 256>>>();
    k_dncomb<<<BS * NPNT, 256>>>(dn_b, dn_g, dn_bt);
    k_spnbr<<<BS, 256>>>(sparse);
    k_spout<<<BS * NSTK, 256>>>(sp_W, sp_b, sp_g, sp_bt);
    k_dsconv<<<BS * NHALF * 4, 256>>>(ds_w, ds_b, ds_g, ds_bt, out);
    k_out_sp<<<64, 256>>>(out);
    k_out_coor<<<32, 256>>>(coor, out);
}

// round 16
// speedup vs baseline: 1.4766x; 1.0596x over previous
#include <cuda_runtime.h>
#include <cuda_bf16.h>
#include <cstdint>

#define BS 4
#define NSTK 32
#define NSPP 128
#define NPNT 4096
#define CIN 128
#define CU 256
#define COUT 256
#define KDN 10
#define NHALF 16
#define COOR 128
#define INF_F 3.402823466e+38f

#define OUT_OFF_DN 16384
#define OUT_OFF_COOR (16384 + 1048576)

// ---------------- static scratch ----------------
__device__ float g_spfd[BS * CIN * NSTK];
__device__ float g_xt[(size_t)BS * NPNT * CU];       // union_dense [b][n][c]
__device__ __nv_bfloat16 g_xh[(size_t)BS * NPNT * CU];
__device__ __nv_bfloat16 g_xl[(size_t)BS * NPNT * CU];
__device__ float g_sqd[BS * NPNT];
__device__ float g_dist[(size_t)BS * NPNT * NPNT];   // 256 MB
__device__ int   g_nbr[BS * NPNT * KDN];
__device__ __nv_bfloat16 g_wth[512 * 256];           // [Wd | W2]^T hi  [n][k]
__device__ __nv_bfloat16 g_wtl[512 * 256];           // lo
__device__ float g_A[(size_t)BS * NPNT * COUT];
__device__ float g_Bm[(size_t)BS * NPNT * COUT];
__device__ float g_dup[(size_t)BS * NPNT * COUT];
__device__ float g_xs[BS * NSTK * CU];
__device__ int   g_spnb[BS * NSTK * 2];
__device__ float g_sup[BS * COUT * NSTK];
__device__ int   g_fps[BS * NHALF];

#define MMA16816(C, A, B) \
    asm volatile("mma.sync.aligned.m16n8k16.row.col.f32.bf16.bf16.f32 " \
        "{%0,%1,%2,%3}, {%4,%5,%6,%7}, {%8,%9}, {%0,%1,%2,%3};" \
        : "+f"((C)[0]), "+f"((C)[1]), "+f"((C)[2]), "+f"((C)[3]) \
        : "r"((A)[0]), "r"((A)[1]), "r"((A)[2]), "r"((A)[3]), "r"((B)[0]), "r"((B)[1]))

#define LDMX4(R, ADDR) \
    asm volatile("ldmatrix.sync.aligned.m8n8.x4.shared.b16 {%0,%1,%2,%3}, [%4];" \
        : "=r"((R)[0]), "=r"((R)[1]), "=r"((R)[2]), "=r"((R)[3]) : "r"(ADDR))

#define LDMX2(R, ADDR) \
    asm volatile("ldmatrix.sync.aligned.m8n8.x2.shared.b16 {%0,%1}, [%2];" \
        : "=r"((R)[0]), "=r"((R)[1]) : "r"(ADDR))

#define CPA16(dst, src) \
    asm volatile("cp.async.ca.shared.global [%0], [%1], 16;" :: "r"(dst), "l"(src))
#define CPA_COMMIT() asm volatile("cp.async.commit_group;" ::: "memory")
#define CPA_WAIT(N)  asm volatile("cp.async.wait_group %0;" :: "n"(N) : "memory")

#define PAD 40
#define ARR_B (128 * PAD * 2)          // bytes per 128xPAD bf16 array = 10240
#define STAGE_B (4 * ARR_B)            // 40960
#define PIPE_SMEM (2 * STAGE_B)        // 81920

// ---------------- W split + transpose: [Wd | W2]^T ----------------
__global__ void k_wsplit(const float* __restrict__ dnW) {
    int idx = blockIdx.x * 256 + threadIdx.x;        // 131072
    int k = idx & 255, n = idx >> 8;
    float v = (n < 256) ? dnW[k * 256 + n] - dnW[(k + 256) * 256 + n]
                        : dnW[(k + 256) * 256 + (n - 256)];
    __nv_bfloat16 h = __float2bfloat16(v);
    g_wth[idx] = h;
    g_wtl[idx] = __float2bfloat16(v - __bfloat162float(h));
}

// ---------------- FPS (exact reference loop) ----------------
__global__ void k_fps(const float* __restrict__ coor) {
    __shared__ float xs[NSTK][COOR];
    __shared__ float dist[NSTK];
    __shared__ int far_s;
    int b = blockIdx.x, tid = threadIdx.x;
    for (int e = tid; e < NSTK * COOR; e += 128)
        xs[e / COOR][e % COOR] = coor[(size_t)b * NSTK * COOR + e];
    if (tid < NSTK) dist[tid] = 1e10f;
    if (tid == 0) far_s = 0;
    __syncthreads();
    for (int it = 0; it < NHALF; ++it) {
        int far = far_s;
        if (tid == 0) g_fps[b * NHALF + it] = far;
        if (tid < NSTK) {
            float d = 0.f;
            for (int c = 0; c < COOR; ++c) { float t = xs[tid][c] - xs[far][c]; d += t * t; }
            dist[tid] = fminf(dist[tid], d);
        }
        __syncthreads();
        if (tid == 0) {
            float bd = dist[0]; int bi = 0;
            for (int j = 1; j < NSTK; ++j) if (dist[j] > bd) { bd = dist[j]; bi = j; }
            far_s = bi;
        }
        __syncthreads();
    }
}

// ---------------- DenseToSparse conv(1,3)+BN+relu+max ----------------
__global__ void __launch_bounds__(256) k_d2s(const float* __restrict__ dense,
                                             const float* __restrict__ w,
                                             const float* __restrict__ bias,
                                             const float* __restrict__ gg,
                                             const float* __restrict__ bt) {
    __shared__ float dfs[64][132];
    __shared__ float red[128];
    int b = blockIdx.x >> 5, s = blockIdx.x & 31;
    int tid = threadIdx.x;
    int o = tid & 127, half = tid >> 7;
    const float* src = dense + (size_t)b * CIN * NPNT + (size_t)s * NSPP;
    const float* wrow = w + (size_t)o * CIN * 3;
    float acc[64];
#pragma unroll
    for (int t = 0; t < 64; ++t) acc[t] = 0.f;
    for (int ch = 0; ch < 2; ++ch) {
        int ci = ch * 64;
        __syncthreads();
        for (int e = tid; e < 64 * 128; e += 256)
            dfs[e >> 7][e & 127] = src[(size_t)(ci + (e >> 7)) * NPNT + (e & 127)];
        if (tid < 64) {
            dfs[tid][128] = 0.f; dfs[tid][129] = 0.f;
            dfs[tid][130] = 0.f; dfs[tid][131] = 0.f;
        }
        __syncthreads();
        for (int i = 0; i < 64; ++i) {
            float w0 = __ldg(wrow + (ci + i) * 3 + 0);
            float w1 = __ldg(wrow + (ci + i) * 3 + 1);
            float w2 = __ldg(wrow + (ci + i) * 3 + 2);
#pragma unroll
            for (int pc = 0; pc < 8; ++pc) {
                const float4* dp = (const float4*)&dfs[i][half * 64 + pc * 8];
                float4 fa = dp[0], fb = dp[1], fc2 = dp[2];
                float d[10] = {fa.x, fa.y, fa.z, fa.w, fb.x, fb.y, fb.z, fb.w, fc2.x, fc2.y};
#pragma unroll
                for (int j = 0; j < 8; ++j)
                    acc[pc * 8 + j] += d[j] * w0 + d[j + 1] * w1 + d[j + 2] * w2;
            }
        }
    }
    float bo = bias[o], go = gg[o], bto = bt[o];
    float mx = -INF_F;
#pragma unroll
    for (int t = 0; t < 64; ++t) {
        int p = half * 64 + t;
        if (p < 126) {
            float h = go * (acc[t] + bo) + bto;
            mx = fmaxf(mx, h > 0.f ? h : 0.f);
        }
    }
    __syncthreads();
    if (half == 0) red[o] = mx;
    __syncthreads();
    if (half == 1)
        g_spfd[((size_t)b * CIN + o) * NSTK + s] = fmaxf(red[o], mx);
}

// ---------------- union_dense transpose ----------------
__global__ void k_txp(const float* __restrict__ dense) {
    __shared__ float tile[32][33];
    int b = blockIdx.z;
    int n0 = blockIdx.x * 32, c0 = blockIdx.y * 32;
    const float* src = dense + (size_t)b * CIN * NPNT;
    for (int j = threadIdx.y; j < 32; j += 8)
        tile[j][threadIdx.x] = src[(size_t)(c0 + j) * NPNT + n0 + threadIdx.x];
    __syncthreads();
    float* dst = g_xt + (size_t)b * NPNT * CU;
    for (int j = threadIdx.y; j < 32; j += 8)
        dst[(size_t)(n0 + j) * CU + c0 + threadIdx.x] = tile[threadIdx.x][j];
}

// ---------------- union_dense sparse broadcast ----------------
__global__ void k_fillsp(const float* __restrict__ sparse) {
    int idx = blockIdx.x * 256 + threadIdx.x;
    int c = idx & 127;
    int bn = idx >> 7;
    int n = bn & (NPNT - 1);
    int b = bn >> 12;
    g_xt[(size_t)(b * NPNT + n) * CU + CIN + c] =
        sparse[((size_t)b * CIN + c) * NSTK + (n >> 7)];
}

// ---------------- bf16 hi/lo split ----------------
__global__ void k_split() {
    size_t idx = (size_t)blockIdx.x * 256 + threadIdx.x;
    float x = g_xt[idx];
    __nv_bfloat16 h = __float2bfloat16(x);
    g_xh[idx] = h;
    g_xl[idx] = __float2bfloat16(x - __bfloat162float(h));
}

// ---------------- per-point squared norm ----------------
__global__ void k_sq() {
    int gw = (blockIdx.x * blockDim.x + threadIdx.x) >> 5;
    int lane = threadIdx.x & 31;
    if (gw >= BS * NPNT) return;
    const float* row = g_xt + (size_t)gw * CU;
    float s = 0.f;
    for (int c = lane; c < CU; c += 32) { float v = row[c]; s += v * v; }
#pragma unroll
    for (int off = 16; off; off >>= 1) s += __shfl_xor_sync(0xffffffffu, s, off);
    if (lane == 0) g_sqd[gw] = s;
}

// ---------------- tensor-core gram: cp.async 2-stage, symmetric, fused mirror ----------------
__global__ void __launch_bounds__(256, 2) k_gram_mma() {
    extern __shared__ char dyn[];
    uint32_t base = (uint32_t)__cvta_generic_to_shared(dyn);
    int b = blockIdx.z, ti = blockIdx.y, tj = blockIdx.x;
    if (ti > tj) return;
    bool mirror = (ti != tj);
    int i0 = ti * 128, j0 = tj * 128;
    const __nv_bfloat16* Xh = g_xh + (size_t)b * NPNT * CU;
    const __nv_bfloat16* Xl = g_xl + (size_t)b * NPNT * CU;
    int tid = threadIdx.x, w = tid >> 5, l = tid & 31;
    int wm = w >> 2, wn = w & 3;
    float c[4][4][4];
#pragma unroll
    for (int mt = 0; mt < 4; ++mt)
#pragma unroll
        for (int nt = 0; nt < 4; ++nt)
#pragma unroll
            for (int q = 0; q < 4; ++q) c[mt][nt][q] = 0.f;

    int arow = wm * 64 + ((l & 8) >> 3) * 8 + (l & 7);
    int acol = (l >> 4) * 8;
    int brow = wn * 32 + (l & 7);
    int bcol = ((l >> 3) & 1) * 8;

    int lrow = tid >> 1, lseg = (tid & 1) * 16;      // 2 threads per row, 16-elem halves

    // prefetch stage 0 (k0 = 0)
    {
        uint32_t sb = base;
#pragma unroll
        for (int h2 = 0; h2 < 2; ++h2) {
            int seg = lseg + h2 * 8;
            uint32_t off = (lrow * PAD + seg) * 2;
            CPA16(sb + off,               (const char*)&Xh[(size_t)(i0 + lrow) * CU + seg]);
            CPA16(sb + ARR_B + off,       (const char*)&Xl[(size_t)(i0 + lrow) * CU + seg]);
            CPA16(sb + 2 * ARR_B + off,   (const char*)&Xh[(size_t)(j0 + lrow) * CU + seg]);
            CPA16(sb + 3 * ARR_B + off,   (const char*)&Xl[(size_t)(j0 + lrow) * CU + seg]);
        }
        CPA_COMMIT();
    }

    for (int i = 0; i < 8; ++i) {
        int cur = i & 1;
        if (i < 7) {
            int k0 = (i + 1) * 32;
            uint32_t sb = base + (cur ^ 1) * STAGE_B;
#pragma unroll
            for (int h2 = 0; h2 < 2; ++h2) {
                int seg = lseg + h2 * 8;
                uint32_t off = (lrow * PAD + seg) * 2;
                CPA16(sb + off,             (const char*)&Xh[(size_t)(i0 + lrow) * CU + k0 + seg]);
                CPA16(sb + ARR_B + off,     (const char*)&Xl[(size_t)(i0 + lrow) * CU + k0 + seg]);
                CPA16(sb + 2 * ARR_B + off, (const char*)&Xh[(size_t)(j0 + lrow) * CU + k0 + seg]);
                CPA16(sb + 3 * ARR_B + off, (const char*)&Xl[(size_t)(j0 + lrow) * CU + k0 + seg]);
            }
            CPA_COMMIT();
            CPA_WAIT(1);
        } else {
            CPA_WAIT(0);
        }
        __syncthreads();
        uint32_t uAh = base + cur * STAGE_B;
        uint32_t uAl = uAh + ARR_B;
        uint32_t uBh = uAh + 2 * ARR_B;
        uint32_t uBl = uAh + 3 * ARR_B;
#pragma unroll
        for (int ks = 0; ks < 2; ++ks) {
            uint32_t ah[4][4], al[4][4], bh[4][2], bl[4][2];
#pragma unroll
            for (int mt = 0; mt < 4; ++mt) {
                uint32_t off = ((arow + mt * 16) * PAD + acol + ks * 16) * 2;
                LDMX4(ah[mt], uAh + off);
                LDMX4(al[mt], uAl + off);
            }
#pragma unroll
            for (int nt = 0; nt < 4; ++nt) {
                uint32_t off = ((brow + nt * 8) * PAD + bcol + ks * 16) * 2;
                LDMX2(bh[nt], uBh + off);
                LDMX2(bl[nt], uBl + off);
            }
#pragma unroll
            for (int mt = 0; mt < 4; ++mt)
#pragma unroll
                for (int nt = 0; nt < 4; ++nt) MMA16816(c[mt][nt], ah[mt], bh[nt]);
#pragma unroll
            for (int mt = 0; mt < 4; ++mt)
#pragma unroll
                for (int nt = 0; nt < 4; ++nt) MMA16816(c[mt][nt], ah[mt], bl[nt]);
#pragma unroll
            for (int mt = 0; mt < 4; ++mt)
#pragma unroll
                for (int nt = 0; nt < 4; ++nt) MMA16816(c[mt][nt], al[mt], bh[nt]);
        }
        __syncthreads();
    }
    const float* sqb = g_sqd + b * NPNT;
    float* D = g_dist + (size_t)b * NPNT * NPNT;
    int rl = l >> 2, cpair = (l & 3) * 2;
#pragma unroll
    for (int mt = 0; mt < 4; ++mt) {
        int gr0 = i0 + wm * 64 + mt * 16 + rl, gr1 = gr0 + 8;
        float si0 = sqb[gr0], si1 = sqb[gr1];
#pragma unroll
        for (int nt = 0; nt < 4; ++nt) {
            int gc = j0 + wn * 32 + nt * 8 + cpair;
            float sj0 = sqb[gc], sj1 = sqb[gc + 1];
            float d00 = si0 - 2.f * c[mt][nt][0] + sj0;
            float d01 = si0 - 2.f * c[mt][nt][1] + sj1;
            float d10 = si1 - 2.f * c[mt][nt][2] + sj0;
            float d11 = si1 - 2.f * c[mt][nt][3] + sj1;
            *(float2*)&D[(size_t)gr0 * NPNT + gc] = make_float2(d00, d01);
            *(float2*)&D[(size_t)gr1 * NPNT + gc] = make_float2(d10, d11);
            if (mirror) {
                D[(size_t)gc * NPNT + gr0]       = d00;
                D[(size_t)gc * NPNT + gr1]       = d10;
                D[(size_t)(gc + 1) * NPNT + gr0] = d01;
                D[(size_t)(gc + 1) * NPNT + gr1] = d11;
            }
        }
    }
}

// ---------------- top-10 smallest per row (warp/row, float4, stable ties) ----------------
__global__ void k_topk() {
    int gw = (blockIdx.x * blockDim.x + threadIdx.x) >> 5;
    int lane = threadIdx.x & 31;
    if (gw >= BS * NPNT) return;
    const float4* drow4 = (const float4*)(g_dist + (size_t)gw * NPNT);
    float ld[10]; int li[10];
#pragma unroll
    for (int p = 0; p < 10; ++p) { ld[p] = INF_F; li[p] = 0x7fffffff; }
    for (int it = 0; it < 32; ++it) {
        float4 v = drow4[lane + it * 32];
        int jb = (lane + it * 32) * 4;
        float vv[4] = {v.x, v.y, v.z, v.w};
#pragma unroll
        for (int q = 0; q < 4; ++q) {
            float dv = vv[q]; int j = jb + q;
            if (dv < ld[9] || (dv == ld[9] && j < li[9])) {
                ld[9] = dv; li[9] = j;
#pragma unroll
                for (int p = 9; p >= 1; --p) {
                    bool sw = (ld[p] < ld[p - 1]) || (ld[p] == ld[p - 1] && li[p] < li[p - 1]);
                    if (sw) {
                        float td = ld[p]; ld[p] = ld[p - 1]; ld[p - 1] = td;
                        int ti = li[p]; li[p] = li[p - 1]; li[p - 1] = ti;
                    }
                }
            }
        }
    }
    int ptr = 0;
    for (int t = 0; t < KDN; ++t) {
        float cd = INF_F; int ci = 0x7fffffff;
#pragma unroll
        for (int p = 0; p < 10; ++p) if (p == ptr) { cd = ld[p]; ci = li[p]; }
        float wd = cd; int wi = ci;
#pragma unroll
        for (int off = 16; off; off >>= 1) {
            float od = __shfl_xor_sync(0xffffffffu, wd, off);
            int oi = __shfl_xor_sync(0xffffffffu, wi, off);
            if (od < wd || (od == wd && oi < wi)) { wd = od; wi = oi; }
        }
        if (ci == wi) ptr++;
        if (lane == 0) g_nbr[gw * KDN + t] = wi;
    }
}

// ---------------- tensor-core GEMM: cp.async 2-stage, [A | Bm] = X @ [Wd | W2] ----------------
__global__ void __launch_bounds__(256, 2) k_gemm_mma() {
    extern __shared__ char dyn[];
    uint32_t base = (uint32_t)__cvta_generic_to_shared(dyn);
    int jt = blockIdx.x, it2 = blockIdx.y;
    int i0 = it2 * 128, j0 = jt * 128;
    int tid = threadIdx.x, w = tid >> 5, l = tid & 31;
    int wm = w >> 2, wn = w & 3;
    float c[4][4][4];
#pragma unroll
    for (int mt = 0; mt < 4; ++mt)
#pragma unroll
        for (int nt = 0; nt < 4; ++nt)
#pragma unroll
            for (int q = 0; q < 4; ++q) c[mt][nt][q] = 0.f;

    int arow = wm * 64 + ((l & 8) >> 3) * 8 + (l & 7);
    int acol = (l >> 4) * 8;
    int brow = wn * 32 + (l & 7);
    int bcol = ((l >> 3) & 1) * 8;
    int lrow = tid >> 1, lseg = (tid & 1) * 16;

    {
        uint32_t sb = base;
#pragma unroll
        for (int h2 = 0; h2 < 2; ++h2) {
            int seg = lseg + h2 * 8;
            uint32_t off = (lrow * PAD + seg) * 2;
            CPA16(sb + off,             (const char*)&g_xh[(size_t)(i0 + lrow) * CU + seg]);
            CPA16(sb + ARR_B + off,     (const char*)&g_xl[(size_t)(i0 + lrow) * CU + seg]);
            CPA16(sb + 2 * ARR_B + off, (const char*)&g_wth[(size_t)(j0 + lrow) * CU + seg]);
            CPA16(sb + 3 * ARR_B + off, (const char*)&g_wtl[(size_t)(j0 + lrow) * CU + seg]);
        }
        CPA_COMMIT();
    }

    for (int i = 0; i < 8; ++i) {
        int cur = i & 1;
        if (i < 7) {
            int k0 = (i + 1) * 32;
            uint32_t sb = base + (cur ^ 1) * STAGE_B;
#pragma unroll
            for (int h2 = 0; h2 < 2; ++h2) {
                int seg = lseg + h2 * 8;
                uint32_t off = (lrow * PAD + seg) * 2;
                CPA16(sb + off,             (const char*)&g_xh[(size_t)(i0 + lrow) * CU + k0 + seg]);
                CPA16(sb + ARR_B + off,     (const char*)&g_xl[(size_t)(i0 + lrow) * CU + k0 + seg]);
                CPA16(sb + 2 * ARR_B + off, (const char*)&g_wth[(size_t)(j0 + lrow) * CU + k0 + seg]);
                CPA16(sb + 3 * ARR_B + off, (const char*)&g_wtl[(size_t)(j0 + lrow) * CU + k0 + seg]);
            }
            CPA_COMMIT();
            CPA_WAIT(1);
        } else {
            CPA_WAIT(0);
        }
        __syncthreads();
        uint32_t uAh = base + cur * STAGE_B;
        uint32_t uAl = uAh + ARR_B;
        uint32_t uBh = uAh + 2 * ARR_B;
        uint32_t uBl = uAh + 3 * ARR_B;
#pragma unroll
        for (int ks = 0; ks < 2; ++ks) {
            uint32_t ah[4][4], al[4][4], bh[4][2], bl[4][2];
#pragma unroll
            for (int mt = 0; mt < 4; ++mt) {
                uint32_t off = ((arow + mt * 16) * PAD + acol + ks * 16) * 2;
                LDMX4(ah[mt], uAh + off);
                LDMX4(al[mt], uAl + off);
            }
#pragma unroll
            for (int nt = 0; nt < 4; ++nt) {
                uint32_t off = ((brow + nt * 8) * PAD + bcol + ks * 16) * 2;
                LDMX2(bh[nt], uBh + off);
                LDMX2(bl[nt], uBl + off);
            }
#pragma unroll
            for (int mt = 0; mt < 4; ++mt)
#pragma unroll
                for (int nt = 0; nt < 4; ++nt) MMA16816(c[mt][nt], ah[mt], bh[nt]);
#pragma unroll
            for (int mt = 0; mt < 4; ++mt)
#pragma unroll
                for (int nt = 0; nt < 4; ++nt) MMA16816(c[mt][nt], ah[mt], bl[nt]);
#pragma unroll
            for (int mt = 0; mt < 4; ++mt)
#pragma unroll
                for (int nt = 0; nt < 4; ++nt) MMA16816(c[mt][nt], al[mt], bh[nt]);
        }
        __syncthreads();
    }
    int rl = l >> 2, cpair = (l & 3) * 2;
#pragma unroll
    for (int mt = 0; mt < 4; ++mt) {
        int gr0 = i0 + wm * 64 + mt * 16 + rl, gr1 = gr0 + 8;
#pragma unroll
        for (int nt = 0; nt < 4; ++nt) {
            int gc = j0 + wn * 32 + nt * 8 + cpair;
            float* Y = (gc < 256) ? g_A : g_Bm;
            int col = gc & 255;
            *(float2*)&Y[(size_t)gr0 * COUT + col] = make_float2(c[mt][nt][0], c[mt][nt][1]);
            *(float2*)&Y[(size_t)gr1 * COUT + col] = make_float2(c[mt][nt][2], c[mt][nt][3]);
        }
    }
}

// ---------------- dense combine ----------------
__global__ void k_dncomb(const float* __restrict__ bb, const float* __restrict__ gg,
                         const float* __restrict__ bt) {
    int bn = blockIdx.x;
    int o = threadIdx.x;
    int b = bn >> 12;
    float A = g_A[(size_t)bn * COUT + o] + bb[o];
    float go = gg[o], bto = bt[o];
    float mx = -INF_F;
    for (int k = 0; k < KDN; ++k) {
        int nb = g_nbr[bn * KDN + k];
        float h = go * (A + g_Bm[(size_t)(b * NPNT + nb) * COUT + o]) + bto;
        mx = fmaxf(mx, h > 0.f ? h : 0.f);
    }
    g_dup[(size_t)bn * COUT + o] = mx;
}

// ---------------- sparse GCN: xs + top-2 neighbors ----------------
__global__ void __launch_bounds__(256) k_spnbr(const float* __restrict__ sparse) {
    __shared__ float xs[NSTK][CU];
    __shared__ float sq[NSTK];
    int b = blockIdx.x, tid = threadIdx.x;
    for (int e = tid; e < NSTK * CU; e += 256) {
        int s = e >> 8, c = e & 255;
        float v = (c < CIN) ? sparse[((size_t)b * CIN + c) * NSTK + s]
                            : g_spfd[((size_t)b * CIN + (c - CIN)) * NSTK + s];
        xs[s][c] = v;
        g_xs[(size_t)(b * NSTK + s) * CU + c] = v;
    }
    __syncthreads();
    if (tid < NSTK) {
        float a = 0.f;
        for (int c = 0; c < CU; ++c) { float v = xs[tid][c]; a += v * v; }
        sq[tid] = a;
    }
    __syncthreads();
    if (tid < NSTK) {
        int r = tid;
        float d0 = INF_F, d1 = INF_F;
        int i0 = 0x7fffffff, i1 = 0x7fffffff;
        for (int m = 0; m < NSTK; ++m) {
            float dot = 0.f;
            for (int c = 0; c < CU; ++c) dot += xs[r][c] * xs[m][c];
            float d = sq[r] - 2.f * dot + sq[m];
            if (d < d0 || (d == d0 && m < i0)) { d1 = d0; i1 = i0; d0 = d; i0 = m; }
            else if (d < d1 || (d == d1 && m < i1)) { d1 = d; i1 = m; }
        }
        g_spnb[(b * NSTK + r) * 2 + 0] = i0;
        g_spnb[(b * NSTK + r) * 2 + 1] = i1;
    }
}

// ---------------- sparse edge-conv output ----------------
__global__ void __launch_bounds__(256) k_spout(const float* __restrict__ spW,
                                               const float* __restrict__ bb,
                                               const float* __restrict__ gg,
                                               const float* __restrict__ bt) {
    __shared__ float ctr[CU], n0v[CU], n1v[CU];
    int b = blockIdx.x >> 5, s = blockIdx.x & 31;
    int o = threadIdx.x;
    int m0 = g_spnb[(b * NSTK + s) * 2 + 0];
    int m1 = g_spnb[(b * NSTK + s) * 2 + 1];
    for (int c = o; c < CU; c += 256) {
        ctr[c] = g_xs[(size_t)(b * NSTK + s) * CU + c];
        n0v[c] = g_xs[(size_t)(b * NSTK + m0) * CU + c];
        n1v[c] = g_xs[(size_t)(b * NSTK + m1) * CU + c];
    }
    __syncthreads();
    float A = 0.f, B0 = 0.f, B1 = 0.f;
    for (int c = 0; c < CU; ++c) {
        float w1 = spW[(size_t)c * COUT + o];
        float w2 = spW[(size_t)(c + CU) * COUT + o];
        A += ctr[c] * (w1 - w2);
        B0 += n0v[c] * w2;
        B1 += n1v[c] * w2;
    }
    float bo = bb[o], go = gg[o], bto = bt[o];
    float h0 = go * (A + B0 + bo) + bto; h0 = h0 > 0.f ? h0 : 0.f;
    float h1 = go * (A + B1 + bo) + bto; h1 = h1 > 0.f ? h1 : 0.f;
    g_sup[((size_t)b * COUT + o) * NSTK + s] = fmaxf(h0, h1);
}

// ---------------- downsample conv ----------------
__global__ void __launch_bounds__(256) k_dsconv(const float* __restrict__ w,
                                                const float* __restrict__ bb,
                                                const float* __restrict__ gg,
                                                const float* __restrict__ bt,
                                                float* __restrict__ out) {
    __shared__ float dfs[64][36];
    int blk = blockIdx.x;
    int b = blk >> 6, jsel = (blk >> 2) & 15, pq = blk & 3;
    int o = threadIdx.x;
    int s = g_fps[b * NHALF + jsel];
    float acc[16];
#pragma unroll
    for (int p = 0; p < 16; ++p) acc[p] = 0.f;
    const float* wrow = w + (size_t)o * COUT * 3;
    for (int ch = 0; ch < 4; ++ch) {
        int c0 = ch * 64;
        __syncthreads();
        for (int e = o; e < 64 * 34; e += 256) {
            int ci = e & 63, qi = e >> 6;
            int q = pq * 32 - 1 + qi;
            dfs[ci][qi] = (q >= 0 && q < 128)
                ? g_dup[(size_t)(b * NPNT + s * NSPP + q) * COUT + c0 + ci] : 0.f;
        }
        __syncthreads();
        for (int ci = 0; ci < 64; ++ci) {
            float w0 = __ldg(wrow + (c0 + ci) * 3 + 0);
            float w1 = __ldg(wrow + (c0 + ci) * 3 + 1);
            float w2 = __ldg(wrow + (c0 + ci) * 3 + 2);
#pragma unroll
            for (int p = 0; p < 16; ++p)
                acc[p] += dfs[ci][2 * p] * w0 + dfs[ci][2 * p + 1] * w1 + dfs[ci][2 * p + 2] * w2;
        }
    }
    float bo = bb[o], go = gg[o], bto = bt[o];
    size_t base = OUT_OFF_DN + (((size_t)b * COUT + o) * NHALF + jsel) * 64 + pq * 16;
#pragma unroll
    for (int p = 0; p < 16; ++p) {
        float h = go * (acc[p] + bo) + bto;
        out[base + p] = h > 0.f ? h : 0.f;
    }
}

// ---------------- output gathers ----------------
__global__ void k_out_sp(float* __restrict__ out) {
    int idx = blockIdx.x * 256 + threadIdx.x;
    int j = idx & 15;
    int o = (idx >> 4) & 255;
    int b = idx >> 12;
    int s = g_fps[b * NHALF + j];
    out[idx] = g_sup[((size_t)b * COUT + o) * NSTK + s];
}

__global__ void k_out_coor(const float* __restrict__ coor, float* __restrict__ out) {
    int idx = blockIdx.x * 256 + threadIdx.x;
    int c = idx & 127;
    int j = (idx >> 7) & 15;
    int b = idx >> 11;
    int s = g_fps[b * NHALF + j];
    out[OUT_OFF_COOR + idx] = coor[((size_t)b * NSTK + s) * COOR + c];
}

extern "C" void kernel_launch(void* const* d_in, const int* in_sizes, int n_in,
                              void* d_out, int out_size) {
    const float* sparse = (const float*)d_in[0];
    const float* dense  = (const float*)d_in[1];
    const float* coor   = (const float*)d_in[2];
    const float* d2s_w  = (const float*)d_in[3];
    const float* d2s_b  = (const float*)d_in[4];
    const float* d2s_g  = (const float*)d_in[5];
    const float* d2s_bt = (const float*)d_in[6];
    const float* sp_W   = (const float*)d_in[7];
    const float* sp_b   = (const float*)d_in[8];
    const float* sp_g   = (const float*)d_in[9];
    const float* sp_bt  = (const float*)d_in[10];
    const float* dn_W   = (const float*)d_in[11];
    const float* dn_b   = (const float*)d_in[12];
    const float* dn_g   = (const float*)d_in[13];
    const float* dn_bt  = (const float*)d_in[14];
    const float* ds_w   = (const float*)d_in[15];
    const float* ds_b   = (const float*)d_in[16];
    const float* ds_g   = (const float*)d_in[17];
    const float* ds_bt  = (const float*)d_in[18];
    float* out = (float*)d_out;

    cudaFuncSetAttribute(k_gram_mma, cudaFuncAttributeMaxDynamicSharedMemorySize, PIPE_SMEM);
    cudaFuncSetAttribute(k_gemm_mma, cudaFuncAttributeMaxDynamicSharedMemorySize, PIPE_SMEM);

    k_wsplit<<<512, 256>>>(dn_W);
    k_fps<<<BS, 128>>>(coor);
    k_d2s<<<BS * NSTK, 256>>>(dense, d2s_w, d2s_b, d2s_g, d2s_bt);
    k_txp<<<dim3(NPNT / 32, CIN / 32, BS), dim3(32, 8)>>>(dense);
    k_fillsp<<<(BS * NPNT * CIN) / 256, 256>>>(sparse);
    k_split<<<(BS * NPNT * CU) / 256, 256>>>();
    k_sq<<<(BS * NPNT * 32) / 256, 256>>>();
    k_gram_mma<<<dim3(32, 32, BS), 256, PIPE_SMEM>>>();
    k_topk<<<(BS * NPNT * 32) / 256, 256>>>();
    k_gemm_mma<<<dim3(4, (BS * NPNT) / 128), 256, PIPE_SMEM>>>();
    k_dncomb<<<BS * NPNT, 256>>>(dn_b, dn_g, dn_bt);
    k_spnbr<<<BS, 256>>>(sparse);
    k_spout<<<BS * NSTK, 256>>>(sp_W, sp_b, sp_g, sp_bt);
    k_dsconv<<<BS * NHALF * 4, 256>>>(ds_w, ds_b, ds_g, ds_bt, out);
    k_out_sp<<<64, 256>>>(out);
    k_out_coor<<<32, 256>>>(coor, out);
}

// round 17
// speedup vs baseline: 1.4977x; 1.0143x over previous
#include <cuda_runtime.h>
#include <cuda_bf16.h>
#include <cstdint>

#define BS 4
#define NSTK 32
#define NSPP 128
#define NPNT 4096
#define CIN 128
#define CU 256
#define COUT 256
#define KDN 10
#define NHALF 16
#define COOR 128
#define INF_F 3.402823466e+38f

#define OUT_OFF_DN 16384
#define OUT_OFF_COOR (16384 + 1048576)

// ---------------- static scratch ----------------
__device__ float g_spfd[BS * CIN * NSTK];
__device__ __nv_bfloat16 g_xh[(size_t)BS * NPNT * CU];
__device__ __nv_bfloat16 g_xl[(size_t)BS * NPNT * CU];
__device__ float g_sqd[BS * NPNT];
__device__ float g_dist[(size_t)BS * NPNT * NPNT];   // 256 MB
__device__ int   g_nbr[BS * NPNT * KDN];
__device__ __nv_bfloat16 g_wth[512 * 256];           // [Wd | W2]^T hi  [n][k]
__device__ __nv_bfloat16 g_wtl[512 * 256];           // lo
__device__ float g_A[(size_t)BS * NPNT * COUT];
__device__ float g_Bm[(size_t)BS * NPNT * COUT];
__device__ float g_dup[(size_t)BS * NPNT * COUT];
__device__ float g_xs[BS * NSTK * CU];
__device__ int   g_spnb[BS * NSTK * 2];
__device__ float g_sup[BS * COUT * NSTK];
__device__ int   g_fps[BS * NHALF];

#define MMA16816(C, A, B) \
    asm volatile("mma.sync.aligned.m16n8k16.row.col.f32.bf16.bf16.f32 " \
        "{%0,%1,%2,%3}, {%4,%5,%6,%7}, {%8,%9}, {%0,%1,%2,%3};" \
        : "+f"((C)[0]), "+f"((C)[1]), "+f"((C)[2]), "+f"((C)[3]) \
        : "r"((A)[0]), "r"((A)[1]), "r"((A)[2]), "r"((A)[3]), "r"((B)[0]), "r"((B)[1]))

#define LDMX4(R, ADDR) \
    asm volatile("ldmatrix.sync.aligned.m8n8.x4.shared.b16 {%0,%1,%2,%3}, [%4];" \
        : "=r"((R)[0]), "=r"((R)[1]), "=r"((R)[2]), "=r"((R)[3]) : "r"(ADDR))

#define LDMX2(R, ADDR) \
    asm volatile("ldmatrix.sync.aligned.m8n8.x2.shared.b16 {%0,%1}, [%2];" \
        : "=r"((R)[0]), "=r"((R)[1]) : "r"(ADDR))

#define CPA16(dst, src) \
    asm volatile("cp.async.ca.shared.global [%0], [%1], 16;" :: "r"(dst), "l"(src))
#define CPA_COMMIT() asm volatile("cp.async.commit_group;" ::: "memory")
#define CPA_WAIT(N)  asm volatile("cp.async.wait_group %0;" :: "n"(N) : "memory")

#define PAD 40
#define ARR_B (128 * PAD * 2)          // 10240
#define STAGE_B (4 * ARR_B)            // 40960
#define PIPE_SMEM (2 * STAGE_B)        // 81920

// ---------------- W split + transpose: [Wd | W2]^T ----------------
__global__ void k_wsplit(const float* __restrict__ dnW) {
    int idx = blockIdx.x * 256 + threadIdx.x;        // 131072
    int k = idx & 255, n = idx >> 8;
    float v = (n < 256) ? dnW[k * 256 + n] - dnW[(k + 256) * 256 + n]
                        : dnW[(k + 256) * 256 + (n - 256)];
    __nv_bfloat16 h = __float2bfloat16(v);
    g_wth[idx] = h;
    g_wtl[idx] = __float2bfloat16(v - __bfloat162float(h));
}

// ---------------- FPS (exact reference loop) ----------------
__global__ void k_fps(const float* __restrict__ coor) {
    __shared__ float xs[NSTK][COOR];
    __shared__ float dist[NSTK];
    __shared__ int far_s;
    int b = blockIdx.x, tid = threadIdx.x;
    for (int e = tid; e < NSTK * COOR; e += 128)
        xs[e / COOR][e % COOR] = coor[(size_t)b * NSTK * COOR + e];
    if (tid < NSTK) dist[tid] = 1e10f;
    if (tid == 0) far_s = 0;
    __syncthreads();
    for (int it = 0; it < NHALF; ++it) {
        int far = far_s;
        if (tid == 0) g_fps[b * NHALF + it] = far;
        if (tid < NSTK) {
            float d = 0.f;
            for (int c = 0; c < COOR; ++c) { float t = xs[tid][c] - xs[far][c]; d += t * t; }
            dist[tid] = fminf(dist[tid], d);
        }
        __syncthreads();
        if (tid == 0) {
            float bd = dist[0]; int bi = 0;
            for (int j = 1; j < NSTK; ++j) if (dist[j] > bd) { bd = dist[j]; bi = j; }
            far_s = bi;
        }
        __syncthreads();
    }
}

// ---------------- DenseToSparse conv(1,3)+BN+relu+max ----------------
__global__ void __launch_bounds__(256) k_d2s(const float* __restrict__ dense,
                                             const float* __restrict__ w,
                                             const float* __restrict__ bias,
                                             const float* __restrict__ gg,
                                             const float* __restrict__ bt) {
    __shared__ float dfs[64][132];
    __shared__ float red[128];
    int b = blockIdx.x >> 5, s = blockIdx.x & 31;
    int tid = threadIdx.x;
    int o = tid & 127, half = tid >> 7;
    const float* src = dense + (size_t)b * CIN * NPNT + (size_t)s * NSPP;
    const float* wrow = w + (size_t)o * CIN * 3;
    float acc[64];
#pragma unroll
    for (int t = 0; t < 64; ++t) acc[t] = 0.f;
    for (int ch = 0; ch < 2; ++ch) {
        int ci = ch * 64;
        __syncthreads();
        for (int e = tid; e < 64 * 128; e += 256)
            dfs[e >> 7][e & 127] = src[(size_t)(ci + (e >> 7)) * NPNT + (e & 127)];
        if (tid < 64) {
            dfs[tid][128] = 0.f; dfs[tid][129] = 0.f;
            dfs[tid][130] = 0.f; dfs[tid][131] = 0.f;
        }
        __syncthreads();
        for (int i = 0; i < 64; ++i) {
            float w0 = __ldg(wrow + (ci + i) * 3 + 0);
            float w1 = __ldg(wrow + (ci + i) * 3 + 1);
            float w2 = __ldg(wrow + (ci + i) * 3 + 2);
#pragma unroll
            for (int pc = 0; pc < 8; ++pc) {
                const float4* dp = (const float4*)&dfs[i][half * 64 + pc * 8];
                float4 fa = dp[0], fb = dp[1], fc2 = dp[2];
                float d[10] = {fa.x, fa.y, fa.z, fa.w, fb.x, fb.y, fb.z, fb.w, fc2.x, fc2.y};
#pragma unroll
                for (int j = 0; j < 8; ++j)
                    acc[pc * 8 + j] += d[j] * w0 + d[j + 1] * w1 + d[j + 2] * w2;
            }
        }
    }
    float bo = bias[o], go = gg[o], bto = bt[o];
    float mx = -INF_F;
#pragma unroll
    for (int t = 0; t < 64; ++t) {
        int p = half * 64 + t;
        if (p < 126) {
            float h = go * (acc[t] + bo) + bto;
            mx = fmaxf(mx, h > 0.f ? h : 0.f);
        }
    }
    __syncthreads();
    if (half == 0) red[o] = mx;
    __syncthreads();
    if (half == 1)
        g_spfd[((size_t)b * CIN + o) * NSTK + s] = fmaxf(red[o], mx);
}

// ---------------- fused prep: transpose + broadcast + bf16 split + sq ----------------
// grid (128 n-tiles, BS), block (32, 8). sq accumulation order/tree bit-identical to old k_sq.
__global__ void __launch_bounds__(256) k_prep(const float* __restrict__ dense,
                                              const float* __restrict__ sparse) {
    __shared__ float tile[32][33];
    int b = blockIdx.y;
    int n0 = blockIdx.x * 32;
    int tx = threadIdx.x, ty = threadIdx.y;
    int s = n0 >> 7;
    float sqa[4] = {0.f, 0.f, 0.f, 0.f};
    __nv_bfloat16* Xh = g_xh + (size_t)b * NPNT * CU;
    __nv_bfloat16* Xl = g_xl + (size_t)b * NPNT * CU;
    const float* src = dense + (size_t)b * CIN * NPNT;
    for (int ct = 0; ct < 4; ++ct) {
        int c0 = ct * 32;
        __syncthreads();
        for (int j = ty; j < 32; j += 8)
            tile[j][tx] = src[(size_t)(c0 + j) * NPNT + n0 + tx];
        __syncthreads();
#pragma unroll
        for (int q = 0; q < 4; ++q) {
            int j = ty + q * 8;
            float x = tile[tx][j];
            __nv_bfloat16 h = __float2bfloat16(x);
            Xh[(size_t)(n0 + j) * CU + c0 + tx] = h;
            Xl[(size_t)(n0 + j) * CU + c0 + tx] = __float2bfloat16(x - __bfloat162float(h));
            sqa[q] += x * x;
        }
    }
#pragma unroll
    for (int ct = 0; ct < 4; ++ct) {
        int c0 = 128 + ct * 32;
        float x = sparse[((size_t)b * CIN + (c0 - 128 + tx)) * NSTK + s];
        __nv_bfloat16 h = __float2bfloat16(x);
        __nv_bfloat16 lo = __float2bfloat16(x - __bfloat162float(h));
#pragma unroll
        for (int q = 0; q < 4; ++q) {
            int j = ty + q * 8;
            Xh[(size_t)(n0 + j) * CU + c0 + tx] = h;
            Xl[(size_t)(n0 + j) * CU + c0 + tx] = lo;
            sqa[q] += x * x;
        }
    }
#pragma unroll
    for (int q = 0; q < 4; ++q) {
        float v = sqa[q];
#pragma unroll
        for (int off = 16; off; off >>= 1) v += __shfl_xor_sync(0xffffffffu, v, off);
        if (tx == 0) g_sqd[b * NPNT + n0 + ty + q * 8] = v;
    }
}

// ---------------- tensor-core gram: cp.async 2-stage, symmetric, fused mirror ----------------
__global__ void __launch_bounds__(256) k_gram_mma() {
    extern __shared__ char dyn[];
    uint32_t base = (uint32_t)__cvta_generic_to_shared(dyn);
    int b = blockIdx.z, ti = blockIdx.y, tj = blockIdx.x;
    if (ti > tj) return;
    bool mirror = (ti != tj);
    int i0 = ti * 128, j0 = tj * 128;
    const __nv_bfloat16* Xh = g_xh + (size_t)b * NPNT * CU;
    const __nv_bfloat16* Xl = g_xl + (size_t)b * NPNT * CU;
    int tid = threadIdx.x, w = tid >> 5, l = tid & 31;
    int wm = w >> 2, wn = w & 3;
    float c[4][4][4];
#pragma unroll
    for (int mt = 0; mt < 4; ++mt)
#pragma unroll
        for (int nt = 0; nt < 4; ++nt)
#pragma unroll
            for (int q = 0; q < 4; ++q) c[mt][nt][q] = 0.f;

    int arow = wm * 64 + ((l & 8) >> 3) * 8 + (l & 7);
    int acol = (l >> 4) * 8;
    int brow = wn * 32 + (l & 7);
    int bcol = ((l >> 3) & 1) * 8;
    int lrow = tid >> 1, lseg = (tid & 1) * 16;

    {
        uint32_t sb = base;
#pragma unroll
        for (int h2 = 0; h2 < 2; ++h2) {
            int seg = lseg + h2 * 8;
            uint32_t off = (lrow * PAD + seg) * 2;
            CPA16(sb + off,             (const char*)&Xh[(size_t)(i0 + lrow) * CU + seg]);
            CPA16(sb + ARR_B + off,     (const char*)&Xl[(size_t)(i0 + lrow) * CU + seg]);
            CPA16(sb + 2 * ARR_B + off, (const char*)&Xh[(size_t)(j0 + lrow) * CU + seg]);
            CPA16(sb + 3 * ARR_B + off, (const char*)&Xl[(size_t)(j0 + lrow) * CU + seg]);
        }
        CPA_COMMIT();
    }

    for (int i = 0; i < 8; ++i) {
        int cur = i & 1;
        if (i < 7) {
            int k0 = (i + 1) * 32;
            uint32_t sb = base + (cur ^ 1) * STAGE_B;
#pragma unroll
            for (int h2 = 0; h2 < 2; ++h2) {
                int seg = lseg + h2 * 8;
                uint32_t off = (lrow * PAD + seg) * 2;
                CPA16(sb + off,             (const char*)&Xh[(size_t)(i0 + lrow) * CU + k0 + seg]);
                CPA16(sb + ARR_B + off,     (const char*)&Xl[(size_t)(i0 + lrow) * CU + k0 + seg]);
                CPA16(sb + 2 * ARR_B + off, (const char*)&Xh[(size_t)(j0 + lrow) * CU + k0 + seg]);
                CPA16(sb + 3 * ARR_B + off, (const char*)&Xl[(size_t)(j0 + lrow) * CU + k0 + seg]);
            }
            CPA_COMMIT();
            CPA_WAIT(1);
        } else {
            CPA_WAIT(0);
        }
        __syncthreads();
        uint32_t uAh = base + cur * STAGE_B;
        uint32_t uAl = uAh + ARR_B;
        uint32_t uBh = uAh + 2 * ARR_B;
        uint32_t uBl = uAh + 3 * ARR_B;
#pragma unroll
        for (int ks = 0; ks < 2; ++ks) {
            uint32_t ah[4][4], al[4][4], bh[4][2], bl[4][2];
#pragma unroll
            for (int mt = 0; mt < 4; ++mt) {
                uint32_t off = ((arow + mt * 16) * PAD + acol + ks * 16) * 2;
                LDMX4(ah[mt], uAh + off);
                LDMX4(al[mt], uAl + off);
            }
#pragma unroll
            for (int nt = 0; nt < 4; ++nt) {
                uint32_t off = ((brow + nt * 8) * PAD + bcol + ks * 16) * 2;
                LDMX2(bh[nt], uBh + off);
                LDMX2(bl[nt], uBl + off);
            }
#pragma unroll
            for (int mt = 0; mt < 4; ++mt)
#pragma unroll
                for (int nt = 0; nt < 4; ++nt) MMA16816(c[mt][nt], ah[mt], bh[nt]);
#pragma unroll
            for (int mt = 0; mt < 4; ++mt)
#pragma unroll
                for (int nt = 0; nt < 4; ++nt) MMA16816(c[mt][nt], ah[mt], bl[nt]);
#pragma unroll
            for (int mt = 0; mt < 4; ++mt)
#pragma unroll
                for (int nt = 0; nt < 4; ++nt) MMA16816(c[mt][nt], al[mt], bh[nt]);
        }
        __syncthreads();
    }
    const float* sqb = g_sqd + b * NPNT;
    float* D = g_dist + (size_t)b * NPNT * NPNT;
    int rl = l >> 2, cpair = (l & 3) * 2;
#pragma unroll
    for (int mt = 0; mt < 4; ++mt) {
        int gr0 = i0 + wm * 64 + mt * 16 + rl, gr1 = gr0 + 8;
        float si0 = sqb[gr0], si1 = sqb[gr1];
#pragma unroll
        for (int nt = 0; nt < 4; ++nt) {
            int gc = j0 + wn * 32 + nt * 8 + cpair;
            float sj0 = sqb[gc], sj1 = sqb[gc + 1];
            float d00 = si0 - 2.f * c[mt][nt][0] + sj0;
            float d01 = si0 - 2.f * c[mt][nt][1] + sj1;
            float d10 = si1 - 2.f * c[mt][nt][2] + sj0;
            float d11 = si1 - 2.f * c[mt][nt][3] + sj1;
            *(float2*)&D[(size_t)gr0 * NPNT + gc] = make_float2(d00, d01);
            *(float2*)&D[(size_t)gr1 * NPNT + gc] = make_float2(d10, d11);
            if (mirror) {
                D[(size_t)gc * NPNT + gr0]       = d00;
                D[(size_t)gc * NPNT + gr1]       = d10;
                D[(size_t)(gc + 1) * NPNT + gr0] = d01;
                D[(size_t)(gc + 1) * NPNT + gr1] = d11;
            }
        }
    }
}

// ---------------- top-10 smallest per row (warp/row, float4, stable ties) ----------------
__global__ void k_topk() {
    int gw = (blockIdx.x * blockDim.x + threadIdx.x) >> 5;
    int lane = threadIdx.x & 31;
    if (gw >= BS * NPNT) return;
    const float4* drow4 = (const float4*)(g_dist + (size_t)gw * NPNT);
    float ld[10]; int li[10];
#pragma unroll
    for (int p = 0; p < 10; ++p) { ld[p] = INF_F; li[p] = 0x7fffffff; }
    for (int it = 0; it < 32; ++it) {
        float4 v = drow4[lane + it * 32];
        int jb = (lane + it * 32) * 4;
        float vv[4] = {v.x, v.y, v.z, v.w};
#pragma unroll
        for (int q = 0; q < 4; ++q) {
            float dv = vv[q]; int j = jb + q;
            if (dv < ld[9] || (dv == ld[9] && j < li[9])) {
                ld[9] = dv; li[9] = j;
#pragma unroll
                for (int p = 9; p >= 1; --p) {
                    bool sw = (ld[p] < ld[p - 1]) || (ld[p] == ld[p - 1] && li[p] < li[p - 1]);
                    if (sw) {
                        float td = ld[p]; ld[p] = ld[p - 1]; ld[p - 1] = td;
                        int ti = li[p]; li[p] = li[p - 1]; li[p - 1] = ti;
                    }
                }
            }
        }
    }
    int ptr = 0;
    for (int t = 0; t < KDN; ++t) {
        float cd = INF_F; int ci = 0x7fffffff;
#pragma unroll
        for (int p = 0; p < 10; ++p) if (p == ptr) { cd = ld[p]; ci = li[p]; }
        float wd = cd; int wi = ci;
#pragma unroll
        for (int off = 16; off; off >>= 1) {
            float od = __shfl_xor_sync(0xffffffffu, wd, off);
            int oi = __shfl_xor_sync(0xffffffffu, wi, off);
            if (od < wd || (od == wd && oi < wi)) { wd = od; wi = oi; }
        }
        if (ci == wi) ptr++;
        if (lane == 0) g_nbr[gw * KDN + t] = wi;
    }
}

// ---------------- tensor-core GEMM: cp.async 2-stage, [A | Bm] = X @ [Wd | W2] ----------------
__global__ void __launch_bounds__(256) k_gemm_mma() {
    extern __shared__ char dyn[];
    uint32_t base = (uint32_t)__cvta_generic_to_shared(dyn);
    int jt = blockIdx.x, it2 = blockIdx.y;
    int i0 = it2 * 128, j0 = jt * 128;
    int tid = threadIdx.x, w = tid >> 5, l = tid & 31;
    int wm = w >> 2, wn = w & 3;
    float c[4][4][4];
#pragma unroll
    for (int mt = 0; mt < 4; ++mt)
#pragma unroll
        for (int nt = 0; nt < 4; ++nt)
#pragma unroll
            for (int q = 0; q < 4; ++q) c[mt][nt][q] = 0.f;

    int arow = wm * 64 + ((l & 8) >> 3) * 8 + (l & 7);
    int acol = (l >> 4) * 8;
    int brow = wn * 32 + (l & 7);
    int bcol = ((l >> 3) & 1) * 8;
    int lrow = tid >> 1, lseg = (tid & 1) * 16;

    {
        uint32_t sb = base;
#pragma unroll
        for (int h2 = 0; h2 < 2; ++h2) {
            int seg = lseg + h2 * 8;
            uint32_t off = (lrow * PAD + seg) * 2;
            CPA16(sb + off,             (const char*)&g_xh[(size_t)(i0 + lrow) * CU + seg]);
            CPA16(sb + ARR_B + off,     (const char*)&g_xl[(size_t)(i0 + lrow) * CU + seg]);
            CPA16(sb + 2 * ARR_B + off, (const char*)&g_wth[(size_t)(j0 + lrow) * CU + seg]);
            CPA16(sb + 3 * ARR_B + off, (const char*)&g_wtl[(size_t)(j0 + lrow) * CU + seg]);
        }
        CPA_COMMIT();
    }

    for (int i = 0; i < 8; ++i) {
        int cur = i & 1;
        if (i < 7) {
            int k0 = (i + 1) * 32;
            uint32_t sb = base + (cur ^ 1) * STAGE_B;
#pragma unroll
            for (int h2 = 0; h2 < 2; ++h2) {
                int seg = lseg + h2 * 8;
                uint32_t off = (lrow * PAD + seg) * 2;
                CPA16(sb + off,             (const char*)&g_xh[(size_t)(i0 + lrow) * CU + k0 + seg]);
                CPA16(sb + ARR_B + off,     (const char*)&g_xl[(size_t)(i0 + lrow) * CU + k0 + seg]);
                CPA16(sb + 2 * ARR_B + off, (const char*)&g_wth[(size_t)(j0 + lrow) * CU + k0 + seg]);
                CPA16(sb + 3 * ARR_B + off, (const char*)&g_wtl[(size_t)(j0 + lrow) * CU + k0 + seg]);
            }
            CPA_COMMIT();
            CPA_WAIT(1);
        } else {
            CPA_WAIT(0);
        }
        __syncthreads();
        uint32_t uAh = base + cur * STAGE_B;
        uint32_t uAl = uAh + ARR_B;
        uint32_t uBh = uAh + 2 * ARR_B;
        uint32_t uBl = uAh + 3 * ARR_B;
#pragma unroll
        for (int ks = 0; ks < 2; ++ks) {
            uint32_t ah[4][4], al[4][4], bh[4][2], bl[4][2];
#pragma unroll
            for (int mt = 0; mt < 4; ++mt) {
                uint32_t off = ((arow + mt * 16) * PAD + acol + ks * 16) * 2;
                LDMX4(ah[mt], uAh + off);
                LDMX4(al[mt], uAl + off);
            }
#pragma unroll
            for (int nt = 0; nt < 4; ++nt) {
                uint32_t off = ((brow + nt * 8) * PAD + bcol + ks * 16) * 2;
                LDMX2(bh[nt], uBh + off);
                LDMX2(bl[nt], uBl + off);
            }
#pragma unroll
            for (int mt = 0; mt < 4; ++mt)
#pragma unroll
                for (int nt = 0; nt < 4; ++nt) MMA16816(c[mt][nt], ah[mt], bh[nt]);
#pragma unroll
            for (int mt = 0; mt < 4; ++mt)
#pragma unroll
                for (int nt = 0; nt < 4; ++nt) MMA16816(c[mt][nt], ah[mt], bl[nt]);
#pragma unroll
            for (int mt = 0; mt < 4; ++mt)
#pragma unroll
                for (int nt = 0; nt < 4; ++nt) MMA16816(c[mt][nt], al[mt], bh[nt]);
        }
        __syncthreads();
    }
    int rl = l >> 2, cpair = (l & 3) * 2;
#pragma unroll
    for (int mt = 0; mt < 4; ++mt) {
        int gr0 = i0 + wm * 64 + mt * 16 + rl, gr1 = gr0 + 8;
#pragma unroll
        for (int nt = 0; nt < 4; ++nt) {
            int gc = j0 + wn * 32 + nt * 8 + cpair;
            float* Y = (gc < 256) ? g_A : g_Bm;
            int col = gc & 255;
            *(float2*)&Y[(size_t)gr0 * COUT + col] = make_float2(c[mt][nt][0], c[mt][nt][1]);
            *(float2*)&Y[(size_t)gr1 * COUT + col] = make_float2(c[mt][nt][2], c[mt][nt][3]);
        }
    }
}

// ---------------- dense combine ----------------
__global__ void k_dncomb(const float* __restrict__ bb, const float* __restrict__ gg,
                         const float* __restrict__ bt) {
    int bn = blockIdx.x;
    int o = threadIdx.x;
    int b = bn >> 12;
    float A = g_A[(size_t)bn * COUT + o] + bb[o];
    float go = gg[o], bto = bt[o];
    float mx = -INF_F;
    for (int k = 0; k < KDN; ++k) {
        int nb = g_nbr[bn * KDN + k];
        float h = go * (A + g_Bm[(size_t)(b * NPNT + nb) * COUT + o]) + bto;
        mx = fmaxf(mx, h > 0.f ? h : 0.f);
    }
    g_dup[(size_t)bn * COUT + o] = mx;
}

// ---------------- sparse GCN: xs + top-2 neighbors ----------------
__global__ void __launch_bounds__(256) k_spnbr(const float* __restrict__ sparse) {
    __shared__ float xs[NSTK][CU];
    __shared__ float sq[NSTK];
    int b = blockIdx.x, tid = threadIdx.x;
    for (int e = tid; e < NSTK * CU; e += 256) {
        int s = e >> 8, c = e & 255;
        float v = (c < CIN) ? sparse[((size_t)b * CIN + c) * NSTK + s]
                            : g_spfd[((size_t)b * CIN + (c - CIN)) * NSTK + s];
        xs[s][c] = v;
        g_xs[(size_t)(b * NSTK + s) * CU + c] = v;
    }
    __syncthreads();
    if (tid < NSTK) {
        float a = 0.f;
        for (int c = 0; c < CU; ++c) { float v = xs[tid][c]; a += v * v; }
        sq[tid] = a;
    }
    __syncthreads();
    if (tid < NSTK) {
        int r = tid;
        float d0 = INF_F, d1 = INF_F;
        int i0 = 0x7fffffff, i1 = 0x7fffffff;
        for (int m = 0; m < NSTK; ++m) {
            float dot = 0.f;
            for (int c = 0; c < CU; ++c) dot += xs[r][c] * xs[m][c];
            float d = sq[r] - 2.f * dot + sq[m];
            if (d < d0 || (d == d0 && m < i0)) { d1 = d0; i1 = i0; d0 = d; i0 = m; }
            else if (d < d1 || (d == d1 && m < i1)) { d1 = d; i1 = m; }
        }
        g_spnb[(b * NSTK + r) * 2 + 0] = i0;
        g_spnb[(b * NSTK + r) * 2 + 1] = i1;
    }
}

// ---------------- sparse edge-conv output ----------------
__global__ void __launch_bounds__(256) k_spout(const float* __restrict__ spW,
                                               const float* __restrict__ bb,
                                               const float* __restrict__ gg,
                                               const float* __restrict__ bt) {
    __shared__ float ctr[CU], n0v[CU], n1v[CU];
    int b = blockIdx.x >> 5, s = blockIdx.x & 31;
    int o = threadIdx.x;
    int m0 = g_spnb[(b * NSTK + s) * 2 + 0];
    int m1 = g_spnb[(b * NSTK + s) * 2 + 1];
    for (int c = o; c < CU; c += 256) {
        ctr[c] = g_xs[(size_t)(b * NSTK + s) * CU + c];
        n0v[c] = g_xs[(size_t)(b * NSTK + m0) * CU + c];
        n1v[c] = g_xs[(size_t)(b * NSTK + m1) * CU + c];
    }
    __syncthreads();
    float A = 0.f, B0 = 0.f, B1 = 0.f;
    for (int c = 0; c < CU; ++c) {
        float w1 = spW[(size_t)c * COUT + o];
        float w2 = spW[(size_t)(c + CU) * COUT + o];
        A += ctr[c] * (w1 - w2);
        B0 += n0v[c] * w2;
        B1 += n1v[c] * w2;
    }
    float bo = bb[o], go = gg[o], bto = bt[o];
    float h0 = go * (A + B0 + bo) + bto; h0 = h0 > 0.f ? h0 : 0.f;
    float h1 = go * (A + B1 + bo) + bto; h1 = h1 > 0.f ? h1 : 0.f;
    g_sup[((size_t)b * COUT + o) * NSTK + s] = fmaxf(h0, h1);
}

// ---------------- downsample conv ----------------
__global__ void __launch_bounds__(256) k_dsconv(const float* __restrict__ w,
                                                const float* __restrict__ bb,
                                                const float* __restrict__ gg,
                                                const float* __restrict__ bt,
                                                float* __restrict__ out) {
    __shared__ float dfs[64][36];
    int blk = blockIdx.x;
    int b = blk >> 6, jsel = (blk >> 2) & 15, pq = blk & 3;
    int o = threadIdx.x;
    int s = g_fps[b * NHALF + jsel];
    float acc[16];
#pragma unroll
    for (int p = 0; p < 16; ++p) acc[p] = 0.f;
    const float* wrow = w + (size_t)o * COUT * 3;
    for (int ch = 0; ch < 4; ++ch) {
        int c0 = ch * 64;
        __syncthreads();
        for (int e = o; e < 64 * 34; e += 256) {
            int ci = e & 63, qi = e >> 6;
            int q = pq * 32 - 1 + qi;
            dfs[ci][qi] = (q >= 0 && q < 128)
                ? g_dup[(size_t)(b * NPNT + s * NSPP + q) * COUT + c0 + ci] : 0.f;
        }
        __syncthreads();
        for (int ci = 0; ci < 64; ++ci) {
            float w0 = __ldg(wrow + (c0 + ci) * 3 + 0);
            float w1 = __ldg(wrow + (c0 + ci) * 3 + 1);
            float w2 = __ldg(wrow + (c0 + ci) * 3 + 2);
#pragma unroll
            for (int p = 0; p < 16; ++p)
                acc[p] += dfs[ci][2 * p] * w0 + dfs[ci][2 * p + 1] * w1 + dfs[ci][2 * p + 2] * w2;
        }
    }
    float bo = bb[o], go = gg[o], bto = bt[o];
    size_t base = OUT_OFF_DN + (((size_t)b * COUT + o) * NHALF + jsel) * 64 + pq * 16;
#pragma unroll
    for (int p = 0; p < 16; ++p) {
        float h = go * (acc[p] + bo) + bto;
        out[base + p] = h > 0.f ? h : 0.f;
    }
}

// ---------------- output gathers ----------------
__global__ void k_out_sp(float* __restrict__ out) {
    int idx = blockIdx.x * 256 + threadIdx.x;
    int j = idx & 15;
    int o = (idx >> 4) & 255;
    int b = idx >> 12;
    int s = g_fps[b * NHALF + j];
    out[idx] = g_sup[((size_t)b * COUT + o) * NSTK + s];
}

__global__ void k_out_coor(const float* __restrict__ coor, float* __restrict__ out) {
    int idx = blockIdx.x * 256 + threadIdx.x;
    int c = idx & 127;
    int j = (idx >> 7) & 15;
    int b = idx >> 11;
    int s = g_fps[b * NHALF + j];
    out[OUT_OFF_COOR + idx] = coor[((size_t)b * NSTK + s) * COOR + c];
}

extern "C" void kernel_launch(void* const* d_in, const int* in_sizes, int n_in,
                              void* d_out, int out_size) {
    const float* sparse = (const float*)d_in[0];
    const float* dense  = (const float*)d_in[1];
    const float* coor   = (const float*)d_in[2];
    const float* d2s_w  = (const float*)d_in[3];
    const float* d2s_b  = (const float*)d_in[4];
    const float* d2s_g  = (const float*)d_in[5];
    const float* d2s_bt = (const float*)d_in[6];
    const float* sp_W   = (const float*)d_in[7];
    const float* sp_b   = (const float*)d_in[8];
    const float* sp_g   = (const float*)d_in[9];
    const float* sp_bt  = (const float*)d_in[10];
    const float* dn_W   = (const float*)d_in[11];
    const float* dn_b   = (const float*)d_in[12];
    const float* dn_g   = (const float*)d_in[13];
    const float* dn_bt  = (const float*)d_in[14];
    const float* ds_w   = (const float*)d_in[15];
    const float* ds_b   = (const float*)d_in[16];
    const float* ds_g   = (const float*)d_in[17];
    const float* ds_bt  = (const float*)d_in[18];
    float* out = (float*)d_out;

    cudaFuncSetAttribute(k_gram_mma, cudaFuncAttributeMaxDynamicSharedMemorySize, PIPE_SMEM);
    cudaFuncSetAttribute(k_gemm_mma, cudaFuncAttributeMaxDynamicSharedMemorySize, PIPE_SMEM);

    k_wsplit<<<512, 256>>>(dn_W);
    k_fps<<<BS, 128>>>(coor);
    k_d2s<<<BS * NSTK, 256>>>(dense, d2s_w, d2s_b, d2s_g, d2s_bt);
    k_prep<<<dim3(NPNT / 32, BS), dim3(32, 8)>>>(dense, sparse);
    k_gram_mma<<<dim3(32, 32, BS), 256, PIPE_SMEM>>>();
    k_topk<<<(BS * NPNT * 32) / 256, 256>>>();
    k_gemm_mma<<<dim3(4, (BS * NPNT) / 128), 256, PIPE_SMEM>>>();
    k_dncomb<<<BS * NPNT, 256>>>(dn_b, dn_g, dn_bt);
    k_spnbr<<<BS, 256>>>(sparse);
    k_spout<<<BS * NSTK, 256>>>(sp_W, sp_b, sp_g, sp_bt);
    k_dsconv<<<BS * NHALF * 4, 256>>>(ds_w, ds_b, ds_g, ds_bt, out);
    k_out_sp<<<64, 256>>>(out);
    k_out_coor<<<32, 256>>>(coor, out);
}